// round 9
// baseline (speedup 1.0000x reference)
#include <cuda_runtime.h>
#include <cuda_bf16.h>
#include <math.h>

#define T_    8
#define H_    28
#define W_    28
#define SP_   6272
#define NTOK  6273
#define DIM_  192
#define HD_   96
#define BROW  68
#define SCALE_ 0.1020620726159658f   // 96^-0.5
#define LOG2E  1.4426950408889634f
#define SCL2   (SCALE_ * LOG2E)

// Scratch (static device memory — no allocations)
__device__ float g_raw [6 * NTOK * HD_];
__device__ float g_pool[6 * NTOK * HD_];
__device__ float g_bias[2 * NTOK * BROW];
__device__ float g_att [NTOK * DIM_];

// ---------------------------------------------------------------------------
__device__ __forceinline__ float cvt_tf32(float x) {
    unsigned u; asm("cvt.rna.tf32.f32 %0, %1;" : "=r"(u) : "f"(x));
    return __uint_as_float(u);
}
__device__ __forceinline__ float fexp2(float x) {
    float y; asm("ex2.approx.ftz.f32 %0, %1;" : "=f"(y) : "f"(x)); return y;
}
__device__ __forceinline__ unsigned pack_bf16(float x, float y) {
    __nv_bfloat162 h = __float22bfloat162_rn(make_float2(x, y));
    return *(unsigned*)&h;
}
__device__ __forceinline__ void mma8(float* d, const float4& a, const float2& b) {
    asm volatile("mma.sync.aligned.m16n8k8.row.col.f32.tf32.tf32.f32 "
        "{%0,%1,%2,%3}, {%4,%5,%6,%7}, {%8,%9}, {%0,%1,%2,%3};"
        : "+f"(d[0]), "+f"(d[1]), "+f"(d[2]), "+f"(d[3])
        : "r"(__float_as_uint(a.x)), "r"(__float_as_uint(a.y)),
          "r"(__float_as_uint(a.z)), "r"(__float_as_uint(a.w)),
          "r"(__float_as_uint(b.x)), "r"(__float_as_uint(b.y)));
}
__device__ __forceinline__ void mma16(float* d, const float4& a, const float2& b) {
    asm volatile("mma.sync.aligned.m16n8k16.row.col.f32.bf16.bf16.f32 "
        "{%0,%1,%2,%3}, {%4,%5,%6,%7}, {%8,%9}, {%0,%1,%2,%3};"
        : "+f"(d[0]), "+f"(d[1]), "+f"(d[2]), "+f"(d[3])
        : "r"(__float_as_uint(a.x)), "r"(__float_as_uint(a.y)),
          "r"(__float_as_uint(a.z)), "r"(__float_as_uint(a.w)),
          "r"(__float_as_uint(b.x)), "r"(__float_as_uint(b.y)));
}

// ---------------------------------------------------------------------------
// tf32 mma GEMM  (unchanged)
// ---------------------------------------------------------------------------
__global__ __launch_bounds__(256) void gemm_mma_kernel(
    const float* __restrict__ A, const float* __restrict__ Bm,
    const float* __restrict__ bias, float* __restrict__ out,
    int M, int N, int mode)
{
    __shared__ float sA[6144];
    __shared__ float sB[6144];
    const float* Ap = (mode == 1) ? g_att : A;

    int tid = threadIdx.x, lane = tid & 31, warp = tid >> 5;
    int mw = warp >> 1, nh = warp & 1;
    int m0 = blockIdx.x * 64, n0 = blockIdx.y * 64;

    float d[4][4] = {};

    for (int k0 = 0; k0 < 192; k0 += 96) {
        __syncthreads();
        {
            int r_g = tid >> 2, r = r_g & 15, mt = r_g >> 4;
            int row = m0 + r_g; if (row >= M) row = M - 1;
            #pragma unroll
            for (int c4 = tid & 3; c4 < 24; c4 += 4) {
                float4 v = *(const float4*)(Ap + row * 192 + k0 + c4 * 4);
                int base = (mt * 12 + (c4 >> 1)) * 128 + (r & 7) * 16
                           + ((r >> 3) & 1) + 2 * (c4 & 1);
                sA[base + 0]  = cvt_tf32(v.x); sA[base + 4]  = cvt_tf32(v.y);
                sA[base + 8]  = cvt_tf32(v.z); sA[base + 12] = cvt_tf32(v.w);
            }
        }
        {
            int r_g = tid >> 2;
            int nt = r_g >> 3, gn = r_g & 7;
            #pragma unroll
            for (int c4 = tid & 3; c4 < 24; c4 += 4) {
                float4 v = *(const float4*)(Bm + (n0 + r_g) * 192 + k0 + c4 * 4);
                int base = (nt * 12 + (c4 >> 1)) * 64 + gn * 8 + (c4 & 1);
                sB[base + 0] = cvt_tf32(v.x); sB[base + 2] = cvt_tf32(v.y);
                sB[base + 4] = cvt_tf32(v.z); sB[base + 6] = cvt_tf32(v.w);
            }
        }
        __syncthreads();
        #pragma unroll
        for (int kt = 0; kt < 12; kt++) {
            float4 a = *(const float4*)(sA + ((mw * 12 + kt) * 32 + lane) * 4);
            #pragma unroll
            for (int nt = 0; nt < 4; nt++) {
                float2 b = *(const float2*)(sB + (((nh * 4 + nt) * 12 + kt) * 32 + lane) * 2);
                mma8(d[nt], a, b);
            }
        }
    }

    int g = lane >> 2, tq = lane & 3;
    int r0 = m0 + mw * 16 + g, r1 = r0 + 8;
    #pragma unroll
    for (int nt = 0; nt < 4; nt++) {
        int col = n0 + nh * 32 + nt * 8 + tq * 2;
        #pragma unroll
        for (int e = 0; e < 2; e++) {
            int c = col + e;
            float b = bias[c];
            float v0 = d[nt][e]     + b;
            float v1 = d[nt][e + 2] + b;
            if (mode == 0) {
                int which = c / DIM_;
                int rem   = c - which * DIM_;
                int head  = rem / HD_;
                int cc    = rem - head * HD_;
                int base  = (which * 2 + head) * NTOK * HD_ + cc;
                if (r0 < M) g_raw[base + r0 * HD_] = v0;
                if (r1 < M) g_raw[base + r1 * HD_] = v1;
            } else {
                if (r0 < M) out[r0 * N + c] = v0;
                if (r1 < M) out[r1 * N + c] = v1;
            }
        }
    }
}

// ---------------------------------------------------------------------------
// Attention pool (unchanged): 1 warp/token, smem weights, shuffle LN
// ---------------------------------------------------------------------------
__global__ __launch_bounds__(256) void pool_kernel(
    const float* __restrict__ wq, const float* __restrict__ wk, const float* __restrict__ wv,
    const float* __restrict__ gq, const float* __restrict__ bq,
    const float* __restrict__ gk, const float* __restrict__ bk,
    const float* __restrict__ gv, const float* __restrict__ bv)
{
    __shared__ float sW[27 * 96];
    int tid = threadIdx.x;
    int yy  = blockIdx.y;
    int tensor = yy >> 1, head = yy & 1;

    const float* wc = (tensor == 0) ? wq : (tensor == 1) ? wk : wv;
    const float* g  = (tensor == 0) ? gq : (tensor == 1) ? gk : gv;
    const float* b  = (tensor == 0) ? bq : (tensor == 1) ? bk : bv;

    for (int i = tid; i < 27 * 96; i += 256) {
        int tap = i / 96, c = i - tap * 96;
        sW[i] = wc[c * 27 + tap];
    }
    __syncthreads();

    int w = tid >> 5, lane = tid & 31;
    int tok = blockIdx.x * 8 + w;
    if (tok < NTOK) {
        const float* in = g_raw + (tensor * 2 + head) * NTOK * HD_;
        float v0, v1, v2;
        if (tok == 0) {
            v0 = in[lane]; v1 = in[lane + 32]; v2 = in[lane + 64];
        } else {
            int s = tok - 1;
            int t = s / 784; int r = s - t * 784;
            int h = r / 28;  int ww = r - h * 28;
            v0 = v1 = v2 = 0.f;
            #pragma unroll
            for (int dt = -1; dt <= 1; dt++) {
                int tt = t + dt; if ((unsigned)tt >= (unsigned)T_) continue;
                #pragma unroll
                for (int dh = -1; dh <= 1; dh++) {
                    int hh = h + dh; if ((unsigned)hh >= (unsigned)H_) continue;
                    #pragma unroll
                    for (int dw = -1; dw <= 1; dw++) {
                        int w2 = ww + dw; if ((unsigned)w2 >= (unsigned)W_) continue;
                        int nb = 1 + (tt * 28 + hh) * 28 + w2;
                        int tap = (dt + 1) * 9 + (dh + 1) * 3 + (dw + 1);
                        const float* p  = in + nb * 96;
                        const float* wr = sW + tap * 96;
                        v0 += p[lane]      * wr[lane];
                        v1 += p[lane + 32] * wr[lane + 32];
                        v2 += p[lane + 64] * wr[lane + 64];
                    }
                }
            }
        }
        float s1 = v0 + v1 + v2;
        float s2 = v0 * v0 + v1 * v1 + v2 * v2;
        #pragma unroll
        for (int o = 1; o < 32; o <<= 1) {
            s1 += __shfl_xor_sync(0xffffffffu, s1, o);
            s2 += __shfl_xor_sync(0xffffffffu, s2, o);
        }
        float mean = s1 * (1.f / 96.f);
        float var  = s2 * (1.f / 96.f) - mean * mean;
        float is   = rsqrtf(var + 1e-5f);
        float* outp = g_pool + (tensor * 2 + head) * NTOK * HD_ + tok * 96;
        outp[lane]      = (v0 - mean) * is * g[lane]      + b[lane];
        outp[lane + 32] = (v1 - mean) * is * g[lane + 32] + b[lane + 32];
        outp[lane + 64] = (v2 - mean) * is * g[lane + 64] + b[lane + 64];
    }
}

// ---------------------------------------------------------------------------
// Rel-bias precompute (unchanged)
#define RSTRIDE 100
__global__ __launch_bounds__(256) void bias_kernel(
    const float* __restrict__ rel_h, const float* __restrict__ rel_w,
    const float* __restrict__ rel_t)
{
    extern __shared__ float bsm[];
    float* sRel = bsm;
    float* sQ   = bsm + 125 * RSTRIDE;
    int head = blockIdx.y;
    int qb = blockIdx.x * 128;
    int tid = threadIdx.x;
    const float* qp = g_pool + head * NTOK * HD_;

    if (blockIdx.x == 0 && tid < BROW)
        g_bias[(head * NTOK) * BROW + tid] = 0.f;

    for (int idx = tid; idx < 125 * 24; idx += 256) {
        int row = idx / 24, c4 = idx - row * 24;
        const float* src = row < 15 ? rel_t + row * 96
                         : row < 70 ? rel_h + (row - 15) * 96
                                    : rel_w + (row - 70) * 96;
        float4 v = *(const float4*)(src + c4 * 4);
        float* dst = sRel + row * RSTRIDE + c4 * 4;
        dst[0] = v.x * LOG2E; dst[1] = v.y * LOG2E;
        dst[2] = v.z * LOG2E; dst[3] = v.w * LOG2E;
    }
    for (int idx = tid; idx < 128 * 24; idx += 256) {
        int r = idx / 24, c4 = idx - r * 24;
        *(float4*)(sQ + r * 96 + c4 * 4) =
            *(const float4*)(qp + (qb + 1 + r) * 96 + c4 * 4);
    }
    __syncthreads();

    for (int it = tid; it < 128 * 64; it += 256) {
        int ql = it >> 6, i = it & 63;
        int s = qb + ql;
        int t = s / 784; int rr = s - t * 784;
        int h = rr / 28; int w = rr - h * 28;
        int row = (i < 8)  ? (t - i + 7)
                : (i < 36) ? 15 + (h - (i - 8) + 27)
                           : 70 + (w - (i - 36) + 27);
        const float* q4 = sQ + ql * 96;
        const float* r4 = sRel + row * RSTRIDE;
        float sum = 0.f;
        #pragma unroll
        for (int c = 0; c < 96; c += 4) {
            float4 a = *(const float4*)(q4 + c);
            float4 b = *(const float4*)(r4 + c);
            sum += a.x*b.x + a.y*b.y + a.z*b.z + a.w*b.w;
        }
        g_bias[(head * NTOK + s + 1) * BROW + i] = sum;
    }
    for (int idx = tid; idx < 128 * 4; idx += 256) {
        int ql = idx >> 2, i = 64 + (idx & 3);
        g_bias[(head * NTOK + qb + 1 + ql) * BROW + i] = 0.f;
    }
}

// ---------------------------------------------------------------------------
// Flash attention v5: m32 register blocking, 6 warps (192 thr), fixed-shift
// softmax + ones-column l. grid (66, 2).
// ---------------------------------------------------------------------------
#define SQ_OFF  0        // 6 mt * 6 kt * 128 = 4608 words
#define SK_OFF  4608     // 2 buf * 3072
#define SV_OFF  10752    // 2 buf * 3328 (13 nt * 4 ktl * 32 * 2)
#define SB_OFF  17408    // 96 * 68 = 6528
#define SKI_OFF 23936    // 2 buf * 64 ints
#define FLASH_SMEM (24064 * 4)
#define NT_TILES 99
#define OSTR 100

__device__ __forceinline__ void stage_kv(
    float* sm, const float* kp, const float* vp, int k0n, int bufn, int tid)
{
    // K -> bf16 B-fragment layout (192 threads)
    {
        float* sKb = sm + SK_OFF + bufn * 3072;
        int r = tid & 63;
        int rowg = k0n + r;
        bool ok = rowg < NTOK;
        int ntk = r >> 3, gnk = r & 7;
        #pragma unroll
        for (int c4 = tid >> 6; c4 < 24; c4 += 3) {
            float4 kv = ok ? *(const float4*)(kp + rowg * 96 + c4 * 4)
                           : make_float4(0.f, 0.f, 0.f, 0.f);
            int p0 = 2 * c4;
            int kt = p0 >> 3, p = p0 & 7;
            unsigned* dK = (unsigned*)sKb + (ntk * 6 + kt) * 64;
            dK[(gnk * 4 + (p & 3)) * 2 + (p >> 2)]   = pack_bf16(kv.x, kv.y);
            int p1 = p + 1;
            dK[(gnk * 4 + (p1 & 3)) * 2 + (p1 >> 2)] = pack_bf16(kv.z, kv.w);
        }
    }
    // V -> bf16 B-fragment layout, key-pair packed; 13th tile = ones column
    {
        unsigned* sVb = (unsigned*)(sm + SV_OFF + bufn * 3328);
        int jp = tid & 31;
        int j0 = k0n + 2 * jp, j1 = j0 + 1;
        int ktv = jp >> 3, pv = jp & 7;
        int wbase = (pv & 3) * 2 + (pv >> 2);
        #pragma unroll
        for (int c4 = tid >> 5; c4 < 25; c4 += 6) {
            if (c4 < 24) {
                float4 v0 = (j0 < NTOK) ? *(const float4*)(vp + j0 * 96 + c4 * 4)
                                        : make_float4(0.f, 0.f, 0.f, 0.f);
                float4 v1 = (j1 < NTOK) ? *(const float4*)(vp + j1 * 96 + c4 * 4)
                                        : make_float4(0.f, 0.f, 0.f, 0.f);
                float a0[4] = {v0.x, v0.y, v0.z, v0.w};
                float a1[4] = {v1.x, v1.y, v1.z, v1.w};
                #pragma unroll
                for (int j = 0; j < 4; j++) {
                    int c = c4 * 4 + j;
                    int ntv = c >> 3, gnv = c & 7;
                    sVb[((ntv * 4 + ktv) * 32 + gnv * 4) * 2 + wbase] = pack_bf16(a0[j], a1[j]);
                }
            } else {
                unsigned one2 = pack_bf16(j0 < NTOK ? 1.f : 0.f,
                                          j1 < NTOK ? 1.f : 0.f);
                sVb[((12 * 4 + ktv) * 32 + 0) * 2 + wbase] = one2;
                #pragma unroll
                for (int gnv = 1; gnv < 8; gnv++)
                    sVb[((12 * 4 + ktv) * 32 + gnv * 4) * 2 + wbase] = 0u;
            }
        }
    }
    if (tid < 64) {
        int* sKIb = (int*)(sm + SKI_OFF) + bufn * 64;
        int kg = k0n + tid;
        int packed;
        if (kg >= NTOK) packed = -1;
        else if (kg == 0) packed = 64 | (65 << 8) | (66 << 16);
        else {
            int ss = kg - 1;
            int t = ss / 784; int rr2 = ss - t * 784;
            int hh = rr2 / 28; int ww = rr2 - hh * 28;
            packed = t | ((8 + hh) << 8) | ((36 + ww) << 16);
        }
        sKIb[tid] = packed;
    }
}

__global__ __launch_bounds__(192, 1) void flash_mma_kernel()
{
    extern __shared__ float sm[];
    float* sQp = sm + SQ_OFF;
    float* sB  = sm + SB_OFF;

    const int head = blockIdx.y;
    const int q0 = blockIdx.x * 96;
    const int tid = threadIdx.x;
    const int lane = tid & 31, warp = tid >> 5;
    const int mw = warp >> 1, nw = warp & 1;   // mw 0..2, nw 0..1

    const float* qp = g_pool + head * NTOK * HD_;
    const float* kp = g_pool + (2 + head) * NTOK * HD_;
    const float* vp = g_pool + (4 + head) * NTOK * HD_;

    // Q -> bf16 A-fragment layout (192 threads: 96 rows, 2 threads/row)
    {
        int r_g = tid >> 1;
        int row = q0 + r_g;
        bool ok = row < NTOK;
        int mt = r_g >> 4, r = r_g & 15;
        int rh = (r >> 3) & 1;
        #pragma unroll
        for (int c4 = tid & 1; c4 < 24; c4 += 2) {
            float4 v = ok ? *(const float4*)(qp + row * 96 + c4 * 4)
                          : make_float4(0.f, 0.f, 0.f, 0.f);
            int p0 = 2 * c4;
            int kt = p0 >> 3, p = p0 & 7;
            unsigned* dst = (unsigned*)sQp + (mt * 6 + kt) * 128;
            dst[((r & 7) * 4 + (p & 3)) * 4 + rh + 2 * (p >> 2)]   = pack_bf16(v.x, v.y);
            int p1 = p + 1;
            dst[((r & 7) * 4 + (p1 & 3)) * 4 + rh + 2 * (p1 >> 2)] = pack_bf16(v.z, v.w);
        }
    }
    // bias rows
    for (int idx = tid; idx < 96 * 17; idx += 192) {
        int r = idx / 17, c4 = idx - r * 17;
        int row = q0 + r; if (row >= NTOK) row = NTOK - 1;
        *(float4*)(sB + r * 68 + c4 * 4) =
            *(const float4*)(g_bias + (head * NTOK + row) * BROW + c4 * 4);
    }
    stage_kv(sm, kp, vp, 0, 0, tid);

    float o0[13][4] = {};      // rows mw*32 + {g, g+8}
    float o1[13][4] = {};      // rows mw*32 + {g+16, g+24}
    const int rloc = mw * 32 + (lane >> 2);
    const float* Br00 = sB + rloc * 68;
    const float* Br01 = Br00 + 8 * 68;
    const float* Br10 = Br00 + 16 * 68;
    const float* Br11 = Br00 + 24 * 68;

    for (int t = 0; t < NT_TILES; t++) {
        int buf = t & 1;
        __syncthreads();
        if (t + 1 < NT_TILES) stage_kv(sm, kp, vp, (t + 1) * 64, buf ^ 1, tid);

        float* sKb = sm + SK_OFF + buf * 3072;
        float* sVb = sm + SV_OFF + buf * 3328;
        int*   sKIb = (int*)(sm + SKI_OFF) + buf * 64;

        // S = Q K^T, m32 x n32 per warp (b fragments reused across m-frags)
        float d0[4][4] = {}, d1[4][4] = {};
        #pragma unroll
        for (int kt = 0; kt < 6; kt++) {
            float4 a0 = *(const float4*)(sQp + (((mw * 2 + 0) * 6 + kt) * 32 + lane) * 4);
            float4 a1 = *(const float4*)(sQp + (((mw * 2 + 1) * 6 + kt) * 32 + lane) * 4);
            #pragma unroll
            for (int nt = 0; nt < 4; nt++) {
                float2 b = *(const float2*)(sKb + (((nw * 4 + nt) * 6 + kt) * 32 + lane) * 2);
                mma16(d0[nt], a0, b);
                mma16(d1[nt], a1, b);
            }
        }

        // scale + bias + mask, p = exp2 (fixed-shift softmax)
        unsigned pk0[2][4], pk1[2][4];
        #pragma unroll
        for (int nt = 0; nt < 4; nt++) {
            int c0 = nw * 32 + nt * 8 + (lane & 3) * 2;
            int p0 = sKIb[c0], p1 = sKIb[c0 + 1];
            if (p0 >= 0) {
                int i0 = p0 & 255, i1 = (p0 >> 8) & 255, i2 = p0 >> 16;
                d0[nt][0] = d0[nt][0] * SCL2 + (Br00[i0] + Br00[i1] + Br00[i2]);
                d0[nt][2] = d0[nt][2] * SCL2 + (Br01[i0] + Br01[i1] + Br01[i2]);
                d1[nt][0] = d1[nt][0] * SCL2 + (Br10[i0] + Br10[i1] + Br10[i2]);
                d1[nt][2] = d1[nt][2] * SCL2 + (Br11[i0] + Br11[i1] + Br11[i2]);
            } else {
                d0[nt][0] = -1e30f; d0[nt][2] = -1e30f;
                d1[nt][0] = -1e30f; d1[nt][2] = -1e30f;
            }
            if (p1 >= 0) {
                int i0 = p1 & 255, i1 = (p1 >> 8) & 255, i2 = p1 >> 16;
                d0[nt][1] = d0[nt][1] * SCL2 + (Br00[i0] + Br00[i1] + Br00[i2]);
                d0[nt][3] = d0[nt][3] * SCL2 + (Br01[i0] + Br01[i1] + Br01[i2]);
                d1[nt][1] = d1[nt][1] * SCL2 + (Br10[i0] + Br10[i1] + Br10[i2]);
                d1[nt][3] = d1[nt][3] * SCL2 + (Br11[i0] + Br11[i1] + Br11[i2]);
            } else {
                d0[nt][1] = -1e30f; d0[nt][3] = -1e30f;
                d1[nt][1] = -1e30f; d1[nt][3] = -1e30f;
            }
            pk0[nt >> 1][(nt & 1) * 2 + 0] = pack_bf16(fexp2(d0[nt][0]), fexp2(d0[nt][1]));
            pk0[nt >> 1][(nt & 1) * 2 + 1] = pack_bf16(fexp2(d0[nt][2]), fexp2(d0[nt][3]));
            pk1[nt >> 1][(nt & 1) * 2 + 0] = pack_bf16(fexp2(d1[nt][0]), fexp2(d1[nt][1]));
            pk1[nt >> 1][(nt & 1) * 2 + 1] = pack_bf16(fexp2(d1[nt][2]), fexp2(d1[nt][3]));
        }

        // O += P V  (b fragments reused across m-frags; 13th nt = l)
        #pragma unroll
        for (int ktl = 0; ktl < 2; ktl++) {
            float4 af0 = make_float4(__uint_as_float(pk0[ktl][0]), __uint_as_float(pk0[ktl][1]),
                                     __uint_as_float(pk0[ktl][2]), __uint_as_float(pk0[ktl][3]));
            float4 af1 = make_float4(__uint_as_float(pk1[ktl][0]), __uint_as_float(pk1[ktl][1]),
                                     __uint_as_float(pk1[ktl][2]), __uint_as_float(pk1[ktl][3]));
            #pragma unroll
            for (int nt = 0; nt < 13; nt++) {
                float2 b = *(const float2*)(sVb + ((nt * 4 + nw * 2 + ktl) * 32 + lane) * 2);
                mma16(o0[nt], af0, b);
                mma16(o1[nt], af1, b);
            }
        }
    }

    // extract l, combine split-KV halves
    float l00 = __shfl_sync(0xffffffffu, o0[12][0], lane & 28);
    float l01 = __shfl_sync(0xffffffffu, o0[12][2], lane & 28);
    float l10 = __shfl_sync(0xffffffffu, o1[12][0], lane & 28);
    float l11 = __shfl_sync(0xffffffffu, o1[12][2], lane & 28);

    __syncthreads();
    float* sO  = sm;                 // 96 * OSTR
    float* sLl = sm + 96 * OSTR;     // 96
    int g = lane >> 2, tq = lane & 3;
    int rl0 = mw * 32 + g, rl1 = rl0 + 8, rl2 = rl0 + 16, rl3 = rl0 + 24;

    if (nw == 1) {
        #pragma unroll
        for (int nt = 0; nt < 12; nt++) {
            *(float2*)(sO + rl0 * OSTR + nt * 8 + tq * 2) = make_float2(o0[nt][0], o0[nt][1]);
            *(float2*)(sO + rl1 * OSTR + nt * 8 + tq * 2) = make_float2(o0[nt][2], o0[nt][3]);
            *(float2*)(sO + rl2 * OSTR + nt * 8 + tq * 2) = make_float2(o1[nt][0], o1[nt][1]);
            *(float2*)(sO + rl3 * OSTR + nt * 8 + tq * 2) = make_float2(o1[nt][2], o1[nt][3]);
        }
        if (tq == 0) {
            sLl[rl0] = l00; sLl[rl1] = l01;
            sLl[rl2] = l10; sLl[rl3] = l11;
        }
    }
    __syncthreads();
    if (nw == 0) {
        float inv0 = 1.f / (l00 + sLl[rl0]);
        float inv1 = 1.f / (l01 + sLl[rl1]);
        float inv2 = 1.f / (l10 + sLl[rl2]);
        float inv3 = 1.f / (l11 + sLl[rl3]);
        int r0 = q0 + rl0, r1 = q0 + rl1, r2 = q0 + rl2, r3 = q0 + rl3;
        #pragma unroll
        for (int nt = 0; nt < 12; nt++) {
            int c = nt * 8 + tq * 2;
            if (r0 < NTOK) {
                float2 oo = *(float2*)(sO + rl0 * OSTR + c);
                float x0 = (o0[nt][0] + oo.x) * inv0;
                float x1 = (o0[nt][1] + oo.y) * inv0;
                if (r0 >= 1) { x0 += qp[r0 * 96 + c]; x1 += qp[r0 * 96 + c + 1]; }
                g_att[r0 * 192 + head * 96 + c]     = x0;
                g_att[r0 * 192 + head * 96 + c + 1] = x1;
            }
            if (r1 < NTOK) {
                float2 oo = *(float2*)(sO + rl1 * OSTR + c);
                g_att[r1 * 192 + head * 96 + c]     = (o0[nt][2] + oo.x) * inv1 + qp[r1 * 96 + c];
                g_att[r1 * 192 + head * 96 + c + 1] = (o0[nt][3] + oo.y) * inv1 + qp[r1 * 96 + c + 1];
            }
            if (r2 < NTOK) {
                float2 oo = *(float2*)(sO + rl2 * OSTR + c);
                g_att[r2 * 192 + head * 96 + c]     = (o1[nt][0] + oo.x) * inv2 + qp[r2 * 96 + c];
                g_att[r2 * 192 + head * 96 + c + 1] = (o1[nt][1] + oo.y) * inv2 + qp[r2 * 96 + c + 1];
            }
            if (r3 < NTOK) {
                float2 oo = *(float2*)(sO + rl3 * OSTR + c);
                g_att[r3 * 192 + head * 96 + c]     = (o1[nt][2] + oo.x) * inv3 + qp[r3 * 96 + c];
                g_att[r3 * 192 + head * 96 + c + 1] = (o1[nt][3] + oo.y) * inv3 + qp[r3 * 96 + c + 1];
            }
        }
    }
}

// ---------------------------------------------------------------------------
extern "C" void kernel_launch(void* const* d_in, const int* in_sizes, int n_in,
                              void* d_out, int out_size)
{
    const float* x      = (const float*)d_in[0];
    const float* qkv_w  = (const float*)d_in[1];
    const float* qkv_b  = (const float*)d_in[2];
    const float* proj_w = (const float*)d_in[3];
    const float* proj_b = (const float*)d_in[4];
    const float* pqw    = (const float*)d_in[5];
    const float* pkw    = (const float*)d_in[6];
    const float* pvw    = (const float*)d_in[7];
    const float* nqg    = (const float*)d_in[8];
    const float* nqb    = (const float*)d_in[9];
    const float* nkg    = (const float*)d_in[10];
    const float* nkb    = (const float*)d_in[11];
    const float* nvg    = (const float*)d_in[12];
    const float* nvb    = (const float*)d_in[13];
    const float* rel_h  = (const float*)d_in[14];
    const float* rel_w  = (const float*)d_in[15];
    const float* rel_t  = (const float*)d_in[16];
    float* out = (float*)d_out;

    const int smem_bias = (125 * RSTRIDE + 128 * 96) * 4;
    cudaFuncSetAttribute(flash_mma_kernel, cudaFuncAttributeMaxDynamicSharedMemorySize, FLASH_SMEM);
    cudaFuncSetAttribute(bias_kernel, cudaFuncAttributeMaxDynamicSharedMemorySize, smem_bias);

    dim3 g1(99, 9);
    gemm_mma_kernel<<<g1, 256>>>(x, qkv_w, qkv_b, nullptr, NTOK, 576, 0);

    dim3 g2(785, 6);
    pool_kernel<<<g2, 256>>>(pqw, pkw, pvw, nqg, nqb, nkg, nkb, nvg, nvb);

    dim3 g3(49, 2);
    bias_kernel<<<g3, 256, smem_bias>>>(rel_h, rel_w, rel_t);

    dim3 g4(66, 2);
    flash_mma_kernel<<<g4, 192, FLASH_SMEM>>>();

    dim3 g5(99, 3);
    gemm_mma_kernel<<<g5, 256>>>(nullptr, proj_w, proj_b, out, NTOK, 192, 1);
}

// round 12
// speedup vs baseline: 1.1267x; 1.1267x over previous
#include <cuda_runtime.h>
#include <cuda_bf16.h>
#include <math.h>

#define T_    8
#define H_    28
#define W_    28
#define SP_   6272
#define NTOK  6273
#define DIM_  192
#define HD_   96
#define BROW  68
#define SCALE_ 0.1020620726159658f   // 96^-0.5
#define LOG2E  1.4426950408889634f
#define SCL2   (SCALE_ * LOG2E)

// Scratch (static device memory — no allocations)
__device__ float g_raw [6 * NTOK * HD_];
__device__ float g_pool[6 * NTOK * HD_];
__device__ float g_bias[2 * NTOK * BROW];
__device__ float g_att [NTOK * DIM_];

// ---------------------------------------------------------------------------
__device__ __forceinline__ float cvt_tf32(float x) {
    unsigned u; asm("cvt.rna.tf32.f32 %0, %1;" : "=r"(u) : "f"(x));
    return __uint_as_float(u);
}
__device__ __forceinline__ float fexp2(float x) {
    float y; asm("ex2.approx.ftz.f32 %0, %1;" : "=f"(y) : "f"(x)); return y;
}
__device__ __forceinline__ unsigned pack_bf16(float x, float y) {
    __nv_bfloat162 h = __float22bfloat162_rn(make_float2(x, y));
    return *(unsigned*)&h;
}
__device__ __forceinline__ void mma8(float* d, const float4& a, const float2& b) {
    asm volatile("mma.sync.aligned.m16n8k8.row.col.f32.tf32.tf32.f32 "
        "{%0,%1,%2,%3}, {%4,%5,%6,%7}, {%8,%9}, {%0,%1,%2,%3};"
        : "+f"(d[0]), "+f"(d[1]), "+f"(d[2]), "+f"(d[3])
        : "r"(__float_as_uint(a.x)), "r"(__float_as_uint(a.y)),
          "r"(__float_as_uint(a.z)), "r"(__float_as_uint(a.w)),
          "r"(__float_as_uint(b.x)), "r"(__float_as_uint(b.y)));
}
__device__ __forceinline__ void mma16(float* d, const float4& a, const float2& b) {
    asm volatile("mma.sync.aligned.m16n8k16.row.col.f32.bf16.bf16.f32 "
        "{%0,%1,%2,%3}, {%4,%5,%6,%7}, {%8,%9}, {%0,%1,%2,%3};"
        : "+f"(d[0]), "+f"(d[1]), "+f"(d[2]), "+f"(d[3])
        : "r"(__float_as_uint(a.x)), "r"(__float_as_uint(a.y)),
          "r"(__float_as_uint(a.z)), "r"(__float_as_uint(a.w)),
          "r"(__float_as_uint(b.x)), "r"(__float_as_uint(b.y)));
}

// ---------------------------------------------------------------------------
// tf32 mma GEMM  (unchanged, known-good)
// ---------------------------------------------------------------------------
__global__ __launch_bounds__(256) void gemm_mma_kernel(
    const float* __restrict__ A, const float* __restrict__ Bm,
    const float* __restrict__ bias, float* __restrict__ out,
    int M, int N, int mode)
{
    __shared__ float sA[6144];
    __shared__ float sB[6144];
    const float* Ap = (mode == 1) ? g_att : A;

    int tid = threadIdx.x, lane = tid & 31, warp = tid >> 5;
    int mw = warp >> 1, nh = warp & 1;
    int m0 = blockIdx.x * 64, n0 = blockIdx.y * 64;

    float d[4][4] = {};

    for (int k0 = 0; k0 < 192; k0 += 96) {
        __syncthreads();
        {
            int r_g = tid >> 2, r = r_g & 15, mt = r_g >> 4;
            int row = m0 + r_g; if (row >= M) row = M - 1;
            #pragma unroll
            for (int c4 = tid & 3; c4 < 24; c4 += 4) {
                float4 v = *(const float4*)(Ap + row * 192 + k0 + c4 * 4);
                int base = (mt * 12 + (c4 >> 1)) * 128 + (r & 7) * 16
                           + ((r >> 3) & 1) + 2 * (c4 & 1);
                sA[base + 0]  = cvt_tf32(v.x); sA[base + 4]  = cvt_tf32(v.y);
                sA[base + 8]  = cvt_tf32(v.z); sA[base + 12] = cvt_tf32(v.w);
            }
        }
        {
            int r_g = tid >> 2;
            int nt = r_g >> 3, gn = r_g & 7;
            #pragma unroll
            for (int c4 = tid & 3; c4 < 24; c4 += 4) {
                float4 v = *(const float4*)(Bm + (n0 + r_g) * 192 + k0 + c4 * 4);
                int base = (nt * 12 + (c4 >> 1)) * 64 + gn * 8 + (c4 & 1);
                sB[base + 0] = cvt_tf32(v.x); sB[base + 2] = cvt_tf32(v.y);
                sB[base + 4] = cvt_tf32(v.z); sB[base + 6] = cvt_tf32(v.w);
            }
        }
        __syncthreads();
        #pragma unroll
        for (int kt = 0; kt < 12; kt++) {
            float4 a = *(const float4*)(sA + ((mw * 12 + kt) * 32 + lane) * 4);
            #pragma unroll
            for (int nt = 0; nt < 4; nt++) {
                float2 b = *(const float2*)(sB + (((nh * 4 + nt) * 12 + kt) * 32 + lane) * 2);
                mma8(d[nt], a, b);
            }
        }
    }

    int g = lane >> 2, tq = lane & 3;
    int r0 = m0 + mw * 16 + g, r1 = r0 + 8;
    #pragma unroll
    for (int nt = 0; nt < 4; nt++) {
        int col = n0 + nh * 32 + nt * 8 + tq * 2;
        #pragma unroll
        for (int e = 0; e < 2; e++) {
            int c = col + e;
            float b = bias[c];
            float v0 = d[nt][e]     + b;
            float v1 = d[nt][e + 2] + b;
            if (mode == 0) {
                int which = c / DIM_;
                int rem   = c - which * DIM_;
                int head  = rem / HD_;
                int cc    = rem - head * HD_;
                int base  = (which * 2 + head) * NTOK * HD_ + cc;
                if (r0 < M) g_raw[base + r0 * HD_] = v0;
                if (r1 < M) g_raw[base + r1 * HD_] = v1;
            } else {
                if (r0 < M) out[r0 * N + c] = v0;
                if (r1 < M) out[r1 * N + c] = v1;
            }
        }
    }
}

// ---------------------------------------------------------------------------
// Attention pool (unchanged): 1 warp/token, smem weights, shuffle LN
// ---------------------------------------------------------------------------
__global__ __launch_bounds__(256) void pool_kernel(
    const float* __restrict__ wq, const float* __restrict__ wk, const float* __restrict__ wv,
    const float* __restrict__ gq, const float* __restrict__ bq,
    const float* __restrict__ gk, const float* __restrict__ bk,
    const float* __restrict__ gv, const float* __restrict__ bv)
{
    __shared__ float sW[27 * 96];
    int tid = threadIdx.x;
    int yy  = blockIdx.y;
    int tensor = yy >> 1, head = yy & 1;

    const float* wc = (tensor == 0) ? wq : (tensor == 1) ? wk : wv;
    const float* g  = (tensor == 0) ? gq : (tensor == 1) ? gk : gv;
    const float* b  = (tensor == 0) ? bq : (tensor == 1) ? bk : bv;

    for (int i = tid; i < 27 * 96; i += 256) {
        int tap = i / 96, c = i - tap * 96;
        sW[i] = wc[c * 27 + tap];
    }
    __syncthreads();

    int w = tid >> 5, lane = tid & 31;
    int tok = blockIdx.x * 8 + w;
    if (tok < NTOK) {
        const float* in = g_raw + (tensor * 2 + head) * NTOK * HD_;
        float v0, v1, v2;
        if (tok == 0) {
            v0 = in[lane]; v1 = in[lane + 32]; v2 = in[lane + 64];
        } else {
            int s = tok - 1;
            int t = s / 784; int r = s - t * 784;
            int h = r / 28;  int ww = r - h * 28;
            v0 = v1 = v2 = 0.f;
            #pragma unroll
            for (int dt = -1; dt <= 1; dt++) {
                int tt = t + dt; if ((unsigned)tt >= (unsigned)T_) continue;
                #pragma unroll
                for (int dh = -1; dh <= 1; dh++) {
                    int hh = h + dh; if ((unsigned)hh >= (unsigned)H_) continue;
                    #pragma unroll
                    for (int dw = -1; dw <= 1; dw++) {
                        int w2 = ww + dw; if ((unsigned)w2 >= (unsigned)W_) continue;
                        int nb = 1 + (tt * 28 + hh) * 28 + w2;
                        int tap = (dt + 1) * 9 + (dh + 1) * 3 + (dw + 1);
                        const float* p  = in + nb * 96;
                        const float* wr = sW + tap * 96;
                        v0 += p[lane]      * wr[lane];
                        v1 += p[lane + 32] * wr[lane + 32];
                        v2 += p[lane + 64] * wr[lane + 64];
                    }
                }
            }
        }
        float s1 = v0 + v1 + v2;
        float s2 = v0 * v0 + v1 * v1 + v2 * v2;
        #pragma unroll
        for (int o = 1; o < 32; o <<= 1) {
            s1 += __shfl_xor_sync(0xffffffffu, s1, o);
            s2 += __shfl_xor_sync(0xffffffffu, s2, o);
        }
        float mean = s1 * (1.f / 96.f);
        float var  = s2 * (1.f / 96.f) - mean * mean;
        float is   = rsqrtf(var + 1e-5f);
        float* outp = g_pool + (tensor * 2 + head) * NTOK * HD_ + tok * 96;
        outp[lane]      = (v0 - mean) * is * g[lane]      + b[lane];
        outp[lane + 32] = (v1 - mean) * is * g[lane + 32] + b[lane + 32];
        outp[lane + 64] = (v2 - mean) * is * g[lane + 64] + b[lane + 64];
    }
}

// ---------------------------------------------------------------------------
// Rel-bias precompute (unchanged)
#define RSTRIDE 100
__global__ __launch_bounds__(256) void bias_kernel(
    const float* __restrict__ rel_h, const float* __restrict__ rel_w,
    const float* __restrict__ rel_t)
{
    extern __shared__ float bsm[];
    float* sRel = bsm;
    float* sQ   = bsm + 125 * RSTRIDE;
    int head = blockIdx.y;
    int qb = blockIdx.x * 128;
    int tid = threadIdx.x;
    const float* qp = g_pool + head * NTOK * HD_;

    if (blockIdx.x == 0 && tid < BROW)
        g_bias[(head * NTOK) * BROW + tid] = 0.f;

    for (int idx = tid; idx < 125 * 24; idx += 256) {
        int row = idx / 24, c4 = idx - row * 24;
        const float* src = row < 15 ? rel_t + row * 96
                         : row < 70 ? rel_h + (row - 15) * 96
                                    : rel_w + (row - 70) * 96;
        float4 v = *(const float4*)(src + c4 * 4);
        float* dst = sRel + row * RSTRIDE + c4 * 4;
        dst[0] = v.x * LOG2E; dst[1] = v.y * LOG2E;
        dst[2] = v.z * LOG2E; dst[3] = v.w * LOG2E;
    }
    for (int idx = tid; idx < 128 * 24; idx += 256) {
        int r = idx / 24, c4 = idx - r * 24;
        *(float4*)(sQ + r * 96 + c4 * 4) =
            *(const float4*)(qp + (qb + 1 + r) * 96 + c4 * 4);
    }
    __syncthreads();

    for (int it = tid; it < 128 * 64; it += 256) {
        int ql = it >> 6, i = it & 63;
        int s = qb + ql;
        int t = s / 784; int rr = s - t * 784;
        int h = rr / 28; int w = rr - h * 28;
        int row = (i < 8)  ? (t - i + 7)
                : (i < 36) ? 15 + (h - (i - 8) + 27)
                           : 70 + (w - (i - 36) + 27);
        const float* q4 = sQ + ql * 96;
        const float* r4 = sRel + row * RSTRIDE;
        float sum = 0.f;
        #pragma unroll
        for (int c = 0; c < 96; c += 4) {
            float4 a = *(const float4*)(q4 + c);
            float4 b = *(const float4*)(r4 + c);
            sum += a.x*b.x + a.y*b.y + a.z*b.z + a.w*b.w;
        }
        g_bias[(head * NTOK + s + 1) * BROW + i] = sum;
    }
    for (int idx = tid; idx < 128 * 4; idx += 256) {
        int ql = idx >> 2, i = 64 + (idx & 3);
        g_bias[(head * NTOK + qb + 1 + ql) * BROW + i] = 0.f;
    }
}

// ---------------------------------------------------------------------------
// Flash attention v7: fixed-shift softmax, ones-column l, Q fragments in
// registers, V fragments paired for LDS.128. grid (66,2), block 384.
// ---------------------------------------------------------------------------
#define SQ_OFF  0        // 6 mt * 6 kt * 128 = 4608 words
#define SK_OFF  4608     // 2 buf * 3072
#define SV_OFF  10752    // 2 buf * 3328 (13 nt * 2 * 128)
#define SB_OFF  17408    // 96 * 68 = 6528
#define SKI_OFF 23936    // 2 buf * 64 ints
#define FLASH_SMEM (24064 * 4)
#define NT_TILES 99
#define OSTR 100

__device__ __forceinline__ void stage_kv(
    float* sm, const float* kp, const float* vp, int k0n, int bufn, int tid)
{
    // K -> bf16 B-fragment layout (unchanged)
    {
        float* sKb = sm + SK_OFF + bufn * 3072;
        int r = tid & 63;
        int rowg = k0n + r;
        bool ok = rowg < NTOK;
        int ntk = r >> 3, gnk = r & 7;
        #pragma unroll
        for (int c4 = tid >> 6; c4 < 24; c4 += 6) {
            float4 kv = ok ? *(const float4*)(kp + rowg * 96 + c4 * 4)
                           : make_float4(0.f, 0.f, 0.f, 0.f);
            int p0 = 2 * c4;
            int kt = p0 >> 3, p = p0 & 7;
            unsigned* dK = (unsigned*)sKb + (ntk * 6 + kt) * 64;
            dK[(gnk * 4 + (p & 3)) * 2 + (p >> 2)]   = pack_bf16(kv.x, kv.y);
            int p1 = p + 1;
            dK[(gnk * 4 + (p1 & 3)) * 2 + (p1 >> 2)] = pack_bf16(kv.z, kv.w);
        }
    }
    // V -> paired B-fragment layout: word = ntv*256 + (ktv>>1)*128
    //        + gnv*16 + (pv&3)*4 + (ktv&1)*2 + (pv>>2).  13th tile = ones.
    {
        unsigned* sVb = (unsigned*)(sm + SV_OFF + bufn * 3328);
        int jp = tid & 31;
        int j0 = k0n + 2 * jp, j1 = j0 + 1;
        int ktv = jp >> 3, pv = jp & 7;
        int koff = (ktv >> 1) * 128 + (pv & 3) * 4 + (ktv & 1) * 2 + (pv >> 2);
        #pragma unroll
        for (int c4 = tid >> 5; c4 < 25; c4 += 12) {
            if (c4 < 24) {
                float4 v0 = (j0 < NTOK) ? *(const float4*)(vp + j0 * 96 + c4 * 4)
                                        : make_float4(0.f, 0.f, 0.f, 0.f);
                float4 v1 = (j1 < NTOK) ? *(const float4*)(vp + j1 * 96 + c4 * 4)
                                        : make_float4(0.f, 0.f, 0.f, 0.f);
                float a0[4] = {v0.x, v0.y, v0.z, v0.w};
                float a1[4] = {v1.x, v1.y, v1.z, v1.w};
                #pragma unroll
                for (int j = 0; j < 4; j++) {
                    int c = c4 * 4 + j;
                    int ntv = c >> 3, gnv = c & 7;
                    sVb[ntv * 256 + gnv * 16 + koff] = pack_bf16(a0[j], a1[j]);
                }
            } else {
                unsigned one2 = pack_bf16(j0 < NTOK ? 1.f : 0.f,
                                          j1 < NTOK ? 1.f : 0.f);
                sVb[12 * 256 + 0 + koff] = one2;
                #pragma unroll
                for (int gnv = 1; gnv < 8; gnv++)
                    sVb[12 * 256 + gnv * 16 + koff] = 0u;
            }
        }
    }
    if (tid < 64) {
        int* sKIb = (int*)(sm + SKI_OFF) + bufn * 64;
        int kg = k0n + tid;
        int packed;
        if (kg >= NTOK) packed = -1;
        else if (kg == 0) packed = 64 | (65 << 8) | (66 << 16);
        else {
            int ss = kg - 1;
            int t = ss / 784; int rr2 = ss - t * 784;
            int hh = rr2 / 28; int ww = rr2 - hh * 28;
            packed = t | ((8 + hh) << 8) | ((36 + ww) << 16);
        }
        sKIb[tid] = packed;
    }
}

__global__ __launch_bounds__(384, 1) void flash_mma_kernel()
{
    extern __shared__ float sm[];
    float* sQp = sm + SQ_OFF;
    float* sB  = sm + SB_OFF;

    const int head = blockIdx.y;
    const int q0 = blockIdx.x * 96;
    const int tid = threadIdx.x;
    const int lane = tid & 31, warp = tid >> 5;
    const int mw = warp >> 1, nw = warp & 1;

    const float* qp = g_pool + head * NTOK * HD_;
    const float* kp = g_pool + (2 + head) * NTOK * HD_;
    const float* vp = g_pool + (4 + head) * NTOK * HD_;

    // Q -> bf16 A-fragment layout (staged once, then hoisted to registers)
    {
        int r_g = tid >> 2;
        int row = q0 + r_g;
        bool ok = row < NTOK;
        int mt = r_g >> 4, r = r_g & 15;
        int rh = (r >> 3) & 1;
        #pragma unroll
        for (int c4 = tid & 3; c4 < 24; c4 += 4) {
            float4 v = ok ? *(const float4*)(qp + row * 96 + c4 * 4)
                          : make_float4(0.f, 0.f, 0.f, 0.f);
            int p0 = 2 * c4;
            int kt = p0 >> 3, p = p0 & 7;
            unsigned* dst = (unsigned*)sQp + (mt * 6 + kt) * 128;
            dst[((r & 7) * 4 + (p & 3)) * 4 + rh + 2 * (p >> 2)]   = pack_bf16(v.x, v.y);
            int p1 = p + 1;
            dst[((r & 7) * 4 + (p1 & 3)) * 4 + rh + 2 * (p1 >> 2)] = pack_bf16(v.z, v.w);
        }
    }
    // bias rows
    for (int idx = tid; idx < 96 * 17; idx += 384) {
        int r = idx / 17, c4 = idx - r * 17;
        int row = q0 + r; if (row >= NTOK) row = NTOK - 1;
        *(float4*)(sB + r * 68 + c4 * 4) =
            *(const float4*)(g_bias + (head * NTOK + row) * BROW + c4 * 4);
    }
    stage_kv(sm, kp, vp, 0, 0, tid);
    __syncthreads();

    // hoist Q fragments (tile-invariant)
    float4 aq[6];
    #pragma unroll
    for (int kt = 0; kt < 6; kt++)
        aq[kt] = *(const float4*)(sQp + ((mw * 6 + kt) * 32 + lane) * 4);

    float oacc[13][4] = {};
    const int rloc = mw * 16 + (lane >> 2);
    const float* Br0 = sB + rloc * 68;
    const float* Br1 = Br0 + 8 * 68;

    for (int t = 0; t < NT_TILES; t++) {
        int buf = t & 1;
        if (t > 0) __syncthreads();
        if (t + 1 < NT_TILES) stage_kv(sm, kp, vp, (t + 1) * 64, buf ^ 1, tid);

        float* sKb = sm + SK_OFF + buf * 3072;
        float* sVb = sm + SV_OFF + buf * 3328;
        int*   sKIb = (int*)(sm + SKI_OFF) + buf * 64;

        // S = Q K^T over this warp's key half (Q from registers)
        float d[4][4] = {};
        #pragma unroll
        for (int kt = 0; kt < 6; kt++) {
            #pragma unroll
            for (int nt = 0; nt < 4; nt++) {
                float2 b = *(const float2*)(sKb + (((nw * 4 + nt) * 6 + kt) * 32 + lane) * 2);
                mma16(d[nt], aq[kt], b);
            }
        }

        // scale + bias + mask, then p = exp2(d) (fixed-shift softmax)
        unsigned pk[2][4];
        #pragma unroll
        for (int nt = 0; nt < 4; nt++) {
            int c0 = nw * 32 + nt * 8 + (lane & 3) * 2;
            int p0 = sKIb[c0], p1 = sKIb[c0 + 1];
            if (p0 >= 0) {
                int i0 = p0 & 255, i1 = (p0 >> 8) & 255, i2 = p0 >> 16;
                d[nt][0] = d[nt][0] * SCL2 + (Br0[i0] + Br0[i1] + Br0[i2]);
                d[nt][2] = d[nt][2] * SCL2 + (Br1[i0] + Br1[i1] + Br1[i2]);
            } else { d[nt][0] = -1e30f; d[nt][2] = -1e30f; }
            if (p1 >= 0) {
                int i0 = p1 & 255, i1 = (p1 >> 8) & 255, i2 = p1 >> 16;
                d[nt][1] = d[nt][1] * SCL2 + (Br0[i0] + Br0[i1] + Br0[i2]);
                d[nt][3] = d[nt][3] * SCL2 + (Br1[i0] + Br1[i1] + Br1[i2]);
            } else { d[nt][1] = -1e30f; d[nt][3] = -1e30f; }
            float p00 = fexp2(d[nt][0]), p01 = fexp2(d[nt][1]);
            float p10 = fexp2(d[nt][2]), p11 = fexp2(d[nt][3]);
            pk[nt >> 1][(nt & 1) * 2 + 0] = pack_bf16(p00, p01);
            pk[nt >> 1][(nt & 1) * 2 + 1] = pack_bf16(p10, p11);
        }

        // O += P V  (paired LDS.128 covers both k16 fragments; 13th nt = l)
        float4 af0 = make_float4(__uint_as_float(pk[0][0]), __uint_as_float(pk[0][1]),
                                 __uint_as_float(pk[0][2]), __uint_as_float(pk[0][3]));
        float4 af1 = make_float4(__uint_as_float(pk[1][0]), __uint_as_float(pk[1][1]),
                                 __uint_as_float(pk[1][2]), __uint_as_float(pk[1][3]));
        #pragma unroll
        for (int nt = 0; nt < 13; nt++) {
            float4 b4 = *(const float4*)(sVb + (nt * 2 + nw) * 128 + lane * 4);
            mma16(oacc[nt], af0, make_float2(b4.x, b4.y));
            mma16(oacc[nt], af1, make_float2(b4.z, b4.w));
        }
    }

    // extract l (ones channel, col 96), combine split-KV halves
    float lA = __shfl_sync(0xffffffffu, oacc[12][0], lane & 28);
    float lB = __shfl_sync(0xffffffffu, oacc[12][2], lane & 28);

    __syncthreads();
    float* sO  = sm;                 // 96 * OSTR
    float* sLl = sm + 96 * OSTR;     // 96
    int g = lane >> 2, tq = lane & 3;
    int rl0 = mw * 16 + g, rl1 = rl0 + 8;

    if (nw == 1) {
        #pragma unroll
        for (int nt = 0; nt < 12; nt++) {
            *(float2*)(sO + rl0 * OSTR + nt * 8 + tq * 2) = make_float2(oacc[nt][0], oacc[nt][1]);
            *(float2*)(sO + rl1 * OSTR + nt * 8 + tq * 2) = make_float2(oacc[nt][2], oacc[nt][3]);
        }
        if (tq == 0) { sLl[rl0] = lA; sLl[rl1] = lB; }
    }
    __syncthreads();
    if (nw == 0) {
        float inv0 = 1.f / (lA + sLl[rl0]);
        float inv1 = 1.f / (lB + sLl[rl1]);
        int r0 = q0 + rl0, r1 = q0 + rl1;
        #pragma unroll
        for (int nt = 0; nt < 12; nt++) {
            int c = nt * 8 + tq * 2;
            if (r0 < NTOK) {
                float2 o1 = *(float2*)(sO + rl0 * OSTR + c);
                float x0 = (oacc[nt][0] + o1.x) * inv0;
                float x1 = (oacc[nt][1] + o1.y) * inv0;
                if (r0 >= 1) { x0 += qp[r0 * 96 + c]; x1 += qp[r0 * 96 + c + 1]; }
                g_att[r0 * 192 + head * 96 + c]     = x0;
                g_att[r0 * 192 + head * 96 + c + 1] = x1;
            }
            if (r1 < NTOK) {
                float2 o1 = *(float2*)(sO + rl1 * OSTR + c);
                float x0 = (oacc[nt][2] + o1.x) * inv1;
                float x1 = (oacc[nt][3] + o1.y) * inv1;
                x0 += qp[r1 * 96 + c]; x1 += qp[r1 * 96 + c + 1];
                g_att[r1 * 192 + head * 96 + c]     = x0;
                g_att[r1 * 192 + head * 96 + c + 1] = x1;
            }
        }
    }
}

// ---------------------------------------------------------------------------
extern "C" void kernel_launch(void* const* d_in, const int* in_sizes, int n_in,
                              void* d_out, int out_size)
{
    const float* x      = (const float*)d_in[0];
    const float* qkv_w  = (const float*)d_in[1];
    const float* qkv_b  = (const float*)d_in[2];
    const float* proj_w = (const float*)d_in[3];
    const float* proj_b = (const float*)d_in[4];
    const float* pqw    = (const float*)d_in[5];
    const float* pkw    = (const float*)d_in[6];
    const float* pvw    = (const float*)d_in[7];
    const float* nqg    = (const float*)d_in[8];
    const float* nqb    = (const float*)d_in[9];
    const float* nkg    = (const float*)d_in[10];
    const float* nkb    = (const float*)d_in[11];
    const float* nvg    = (const float*)d_in[12];
    const float* nvb    = (const float*)d_in[13];
    const float* rel_h  = (const float*)d_in[14];
    const float* rel_w  = (const float*)d_in[15];
    const float* rel_t  = (const float*)d_in[16];
    float* out = (float*)d_out;

    const int smem_bias = (125 * RSTRIDE + 128 * 96) * 4;
    cudaFuncSetAttribute(flash_mma_kernel, cudaFuncAttributeMaxDynamicSharedMemorySize, FLASH_SMEM);
    cudaFuncSetAttribute(bias_kernel, cudaFuncAttributeMaxDynamicSharedMemorySize, smem_bias);

    dim3 g1(99, 9);
    gemm_mma_kernel<<<g1, 256>>>(x, qkv_w, qkv_b, nullptr, NTOK, 576, 0);

    dim3 g2(785, 6);
    pool_kernel<<<g2, 256>>>(pqw, pkw, pvw, nqg, nqb, nkg, nkb, nvg, nvb);

    dim3 g3(49, 2);
    bias_kernel<<<g3, 256, smem_bias>>>(rel_h, rel_w, rel_t);

    dim3 g4(66, 2);
    flash_mma_kernel<<<g4, 384, FLASH_SMEM>>>();

    dim3 g5(99, 3);
    gemm_mma_kernel<<<g5, 256>>>(nullptr, proj_w, proj_b, out, NTOK, 192, 1);
}

// round 14
// speedup vs baseline: 1.9299x; 1.7129x over previous
#include <cuda_runtime.h>
#include <cuda_bf16.h>
#include <cstdint>
#include <math.h>

#define T_    8
#define H_    28
#define W_    28
#define SP_   6272
#define NTOK  6273
#define DIM_  192
#define HD_   96
#define BROW  68
#define SCALE_ 0.1020620726159658f   // 96^-0.5
#define LOG2E  1.4426950408889634f
#define SCL2   (SCALE_ * LOG2E)
#define NT_TILES 99

// Scratch (static device memory — no allocations)
__device__ float g_raw [6 * NTOK * HD_];
__device__ float g_pool[6 * NTOK * HD_];
__device__ float g_bias[2 * NTOK * BROW];
__device__ float g_att [NTOK * DIM_];
__device__ unsigned g_kimg[2 * NT_TILES * 3072];  // K fragment-layout images
__device__ unsigned g_vimg[2 * NT_TILES * 3328];  // V fragment-layout images (paired)
__device__ int      g_ki  [NT_TILES * 64];        // packed bias indices per key

// ---------------------------------------------------------------------------
__device__ __forceinline__ float cvt_tf32(float x) {
    unsigned u; asm("cvt.rna.tf32.f32 %0, %1;" : "=r"(u) : "f"(x));
    return __uint_as_float(u);
}
__device__ __forceinline__ float fexp2(float x) {
    float y; asm("ex2.approx.ftz.f32 %0, %1;" : "=f"(y) : "f"(x)); return y;
}
__device__ __forceinline__ unsigned pack_bf16(float x, float y) {
    __nv_bfloat162 h = __float22bfloat162_rn(make_float2(x, y));
    return *(unsigned*)&h;
}
__device__ __forceinline__ void mma8(float* d, const float4& a, const float2& b) {
    asm volatile("mma.sync.aligned.m16n8k8.row.col.f32.tf32.tf32.f32 "
        "{%0,%1,%2,%3}, {%4,%5,%6,%7}, {%8,%9}, {%0,%1,%2,%3};"
        : "+f"(d[0]), "+f"(d[1]), "+f"(d[2]), "+f"(d[3])
        : "r"(__float_as_uint(a.x)), "r"(__float_as_uint(a.y)),
          "r"(__float_as_uint(a.z)), "r"(__float_as_uint(a.w)),
          "r"(__float_as_uint(b.x)), "r"(__float_as_uint(b.y)));
}
__device__ __forceinline__ void mma16(float* d, const float4& a, const float2& b) {
    asm volatile("mma.sync.aligned.m16n8k16.row.col.f32.bf16.bf16.f32 "
        "{%0,%1,%2,%3}, {%4,%5,%6,%7}, {%8,%9}, {%0,%1,%2,%3};"
        : "+f"(d[0]), "+f"(d[1]), "+f"(d[2]), "+f"(d[3])
        : "r"(__float_as_uint(a.x)), "r"(__float_as_uint(a.y)),
          "r"(__float_as_uint(a.z)), "r"(__float_as_uint(a.w)),
          "r"(__float_as_uint(b.x)), "r"(__float_as_uint(b.y)));
}
__device__ __forceinline__ unsigned smem_u32(const void* p) {
    unsigned a;
    asm("{ .reg .u64 t; cvta.to.shared.u64 t, %1; cvt.u32.u64 %0, t; }" : "=r"(a) : "l"(p));
    return a;
}
__device__ __forceinline__ void cp16(unsigned s, const void* g) {
    asm volatile("cp.async.cg.shared.global [%0], [%1], 16;" :: "r"(s), "l"(g) : "memory");
}
#define CP_COMMIT() asm volatile("cp.async.commit_group;" ::: "memory")
#define CP_WAIT0()  asm volatile("cp.async.wait_group 0;" ::: "memory")

// ---------------------------------------------------------------------------
// tf32 mma GEMM  (unchanged, known-good)
// ---------------------------------------------------------------------------
__global__ __launch_bounds__(256) void gemm_mma_kernel(
    const float* __restrict__ A, const float* __restrict__ Bm,
    const float* __restrict__ bias, float* __restrict__ out,
    int M, int N, int mode)
{
    __shared__ float sA[6144];
    __shared__ float sB[6144];
    const float* Ap = (mode == 1) ? g_att : A;

    int tid = threadIdx.x, lane = tid & 31, warp = tid >> 5;
    int mw = warp >> 1, nh = warp & 1;
    int m0 = blockIdx.x * 64, n0 = blockIdx.y * 64;

    float d[4][4] = {};

    for (int k0 = 0; k0 < 192; k0 += 96) {
        __syncthreads();
        {
            int r_g = tid >> 2, r = r_g & 15, mt = r_g >> 4;
            int row = m0 + r_g; if (row >= M) row = M - 1;
            #pragma unroll
            for (int c4 = tid & 3; c4 < 24; c4 += 4) {
                float4 v = *(const float4*)(Ap + row * 192 + k0 + c4 * 4);
                int base = (mt * 12 + (c4 >> 1)) * 128 + (r & 7) * 16
                           + ((r >> 3) & 1) + 2 * (c4 & 1);
                sA[base + 0]  = cvt_tf32(v.x); sA[base + 4]  = cvt_tf32(v.y);
                sA[base + 8]  = cvt_tf32(v.z); sA[base + 12] = cvt_tf32(v.w);
            }
        }
        {
            int r_g = tid >> 2;
            int nt = r_g >> 3, gn = r_g & 7;
            #pragma unroll
            for (int c4 = tid & 3; c4 < 24; c4 += 4) {
                float4 v = *(const float4*)(Bm + (n0 + r_g) * 192 + k0 + c4 * 4);
                int base = (nt * 12 + (c4 >> 1)) * 64 + gn * 8 + (c4 & 1);
                sB[base + 0] = cvt_tf32(v.x); sB[base + 2] = cvt_tf32(v.y);
                sB[base + 4] = cvt_tf32(v.z); sB[base + 6] = cvt_tf32(v.w);
            }
        }
        __syncthreads();
        #pragma unroll
        for (int kt = 0; kt < 12; kt++) {
            float4 a = *(const float4*)(sA + ((mw * 12 + kt) * 32 + lane) * 4);
            #pragma unroll
            for (int nt = 0; nt < 4; nt++) {
                float2 b = *(const float2*)(sB + (((nh * 4 + nt) * 12 + kt) * 32 + lane) * 2);
                mma8(d[nt], a, b);
            }
        }
    }

    int g = lane >> 2, tq = lane & 3;
    int r0 = m0 + mw * 16 + g, r1 = r0 + 8;
    #pragma unroll
    for (int nt = 0; nt < 4; nt++) {
        int col = n0 + nh * 32 + nt * 8 + tq * 2;
        #pragma unroll
        for (int e = 0; e < 2; e++) {
            int c = col + e;
            float b = bias[c];
            float v0 = d[nt][e]     + b;
            float v1 = d[nt][e + 2] + b;
            if (mode == 0) {
                int which = c / DIM_;
                int rem   = c - which * DIM_;
                int head  = rem / HD_;
                int cc    = rem - head * HD_;
                int base  = (which * 2 + head) * NTOK * HD_ + cc;
                if (r0 < M) g_raw[base + r0 * HD_] = v0;
                if (r1 < M) g_raw[base + r1 * HD_] = v1;
            } else {
                if (r0 < M) out[r0 * N + c] = v0;
                if (r1 < M) out[r1 * N + c] = v1;
            }
        }
    }
}

// ---------------------------------------------------------------------------
// Attention pool (unchanged): 1 warp/token, smem weights, shuffle LN
// ---------------------------------------------------------------------------
__global__ __launch_bounds__(256) void pool_kernel(
    const float* __restrict__ wq, const float* __restrict__ wk, const float* __restrict__ wv,
    const float* __restrict__ gq, const float* __restrict__ bq,
    const float* __restrict__ gk, const float* __restrict__ bk,
    const float* __restrict__ gv, const float* __restrict__ bv)
{
    __shared__ float sW[27 * 96];
    int tid = threadIdx.x;
    int yy  = blockIdx.y;
    int tensor = yy >> 1, head = yy & 1;

    const float* wc = (tensor == 0) ? wq : (tensor == 1) ? wk : wv;
    const float* g  = (tensor == 0) ? gq : (tensor == 1) ? gk : gv;
    const float* b  = (tensor == 0) ? bq : (tensor == 1) ? bk : bv;

    for (int i = tid; i < 27 * 96; i += 256) {
        int tap = i / 96, c = i - tap * 96;
        sW[i] = wc[c * 27 + tap];
    }
    __syncthreads();

    int w = tid >> 5, lane = tid & 31;
    int tok = blockIdx.x * 8 + w;
    if (tok < NTOK) {
        const float* in = g_raw + (tensor * 2 + head) * NTOK * HD_;
        float v0, v1, v2;
        if (tok == 0) {
            v0 = in[lane]; v1 = in[lane + 32]; v2 = in[lane + 64];
        } else {
            int s = tok - 1;
            int t = s / 784; int r = s - t * 784;
            int h = r / 28;  int ww = r - h * 28;
            v0 = v1 = v2 = 0.f;
            #pragma unroll
            for (int dt = -1; dt <= 1; dt++) {
                int tt = t + dt; if ((unsigned)tt >= (unsigned)T_) continue;
                #pragma unroll
                for (int dh = -1; dh <= 1; dh++) {
                    int hh = h + dh; if ((unsigned)hh >= (unsigned)H_) continue;
                    #pragma unroll
                    for (int dw = -1; dw <= 1; dw++) {
                        int w2 = ww + dw; if ((unsigned)w2 >= (unsigned)W_) continue;
                        int nb = 1 + (tt * 28 + hh) * 28 + w2;
                        int tap = (dt + 1) * 9 + (dh + 1) * 3 + (dw + 1);
                        const float* p  = in + nb * 96;
                        const float* wr = sW + tap * 96;
                        v0 += p[lane]      * wr[lane];
                        v1 += p[lane + 32] * wr[lane + 32];
                        v2 += p[lane + 64] * wr[lane + 64];
                    }
                }
            }
        }
        float s1 = v0 + v1 + v2;
        float s2 = v0 * v0 + v1 * v1 + v2 * v2;
        #pragma unroll
        for (int o = 1; o < 32; o <<= 1) {
            s1 += __shfl_xor_sync(0xffffffffu, s1, o);
            s2 += __shfl_xor_sync(0xffffffffu, s2, o);
        }
        float mean = s1 * (1.f / 96.f);
        float var  = s2 * (1.f / 96.f) - mean * mean;
        float is   = rsqrtf(var + 1e-5f);
        float* outp = g_pool + (tensor * 2 + head) * NTOK * HD_ + tok * 96;
        outp[lane]      = (v0 - mean) * is * g[lane]      + b[lane];
        outp[lane + 32] = (v1 - mean) * is * g[lane + 32] + b[lane + 32];
        outp[lane + 64] = (v2 - mean) * is * g[lane + 64] + b[lane + 64];
    }
}

// ---------------------------------------------------------------------------
// Rel-bias precompute (unchanged)
#define RSTRIDE 100
__global__ __launch_bounds__(256) void bias_kernel(
    const float* __restrict__ rel_h, const float* __restrict__ rel_w,
    const float* __restrict__ rel_t)
{
    extern __shared__ float bsm[];
    float* sRel = bsm;
    float* sQ   = bsm + 125 * RSTRIDE;
    int head = blockIdx.y;
    int qb = blockIdx.x * 128;
    int tid = threadIdx.x;
    const float* qp = g_pool + head * NTOK * HD_;

    if (blockIdx.x == 0 && tid < BROW)
        g_bias[(head * NTOK) * BROW + tid] = 0.f;

    for (int idx = tid; idx < 125 * 24; idx += 256) {
        int row = idx / 24, c4 = idx - row * 24;
        const float* src = row < 15 ? rel_t + row * 96
                         : row < 70 ? rel_h + (row - 15) * 96
                                    : rel_w + (row - 70) * 96;
        float4 v = *(const float4*)(src + c4 * 4);
        float* dst = sRel + row * RSTRIDE + c4 * 4;
        dst[0] = v.x * LOG2E; dst[1] = v.y * LOG2E;
        dst[2] = v.z * LOG2E; dst[3] = v.w * LOG2E;
    }
    for (int idx = tid; idx < 128 * 24; idx += 256) {
        int r = idx / 24, c4 = idx - r * 24;
        *(float4*)(sQ + r * 96 + c4 * 4) =
            *(const float4*)(qp + (qb + 1 + r) * 96 + c4 * 4);
    }
    __syncthreads();

    for (int it = tid; it < 128 * 64; it += 256) {
        int ql = it >> 6, i = it & 63;
        int s = qb + ql;
        int t = s / 784; int rr = s - t * 784;
        int h = rr / 28; int w = rr - h * 28;
        int row = (i < 8)  ? (t - i + 7)
                : (i < 36) ? 15 + (h - (i - 8) + 27)
                           : 70 + (w - (i - 36) + 27);
        const float* q4 = sQ + ql * 96;
        const float* r4 = sRel + row * RSTRIDE;
        float sum = 0.f;
        #pragma unroll
        for (int c = 0; c < 96; c += 4) {
            float4 a = *(const float4*)(q4 + c);
            float4 b = *(const float4*)(r4 + c);
            sum += a.x*b.x + a.y*b.y + a.z*b.z + a.w*b.w;
        }
        g_bias[(head * NTOK + s + 1) * BROW + i] = sum;
    }
    for (int idx = tid; idx < 128 * 4; idx += 256) {
        int ql = idx >> 2, i = 64 + (idx & 3);
        g_bias[(head * NTOK + qb + 1 + ql) * BROW + i] = 0.f;
    }
}

// ---------------------------------------------------------------------------
// Prep: build fragment-layout K/V images + packed bias-index array in global.
// grid (99, 2), 256 threads.
// ---------------------------------------------------------------------------
__global__ __launch_bounds__(256) void prep_kernel()
{
    int tile = blockIdx.x, head = blockIdx.y;
    int tid = threadIdx.x;
    unsigned* kimg = g_kimg + (head * NT_TILES + tile) * 3072;
    unsigned* vimg = g_vimg + (head * NT_TILES + tile) * 3328;
    const float* kp = g_pool + (2 + head) * NTOK * HD_;
    const float* vp = g_pool + (4 + head) * NTOK * HD_;

    // K: 64 keys x 24 c4-chunks -> B-fragment layout words
    for (int idx = tid; idx < 1536; idx += 256) {
        int r = idx / 24, c4 = idx - r * 24;
        int rowg = tile * 64 + r;
        float4 kv = (rowg < NTOK) ? *(const float4*)(kp + rowg * 96 + c4 * 4)
                                  : make_float4(0.f, 0.f, 0.f, 0.f);
        int ntk = r >> 3, gnk = r & 7;
        int p0 = 2 * c4;
        int kt = p0 >> 3, p = p0 & 7;
        unsigned* dK = kimg + (ntk * 6 + kt) * 64;
        dK[(gnk * 4 + (p & 3)) * 2 + (p >> 2)]   = pack_bf16(kv.x, kv.y);
        int p1 = p + 1;
        dK[(gnk * 4 + (p1 & 3)) * 2 + (p1 >> 2)] = pack_bf16(kv.z, kv.w);
    }
    // V: 32 key-pairs x 25 c4-chunks -> paired B-fragment layout
    for (int idx = tid; idx < 800; idx += 256) {
        int jp = idx / 25, c4 = idx - jp * 25;
        int j0 = tile * 64 + 2 * jp, j1 = j0 + 1;
        int ktv = jp >> 3, pv = jp & 7;
        int koff = (ktv >> 1) * 128 + (pv & 3) * 4 + (ktv & 1) * 2 + (pv >> 2);
        if (c4 < 24) {
            float4 v0 = (j0 < NTOK) ? *(const float4*)(vp + j0 * 96 + c4 * 4)
                                    : make_float4(0.f, 0.f, 0.f, 0.f);
            float4 v1 = (j1 < NTOK) ? *(const float4*)(vp + j1 * 96 + c4 * 4)
                                    : make_float4(0.f, 0.f, 0.f, 0.f);
            float a0[4] = {v0.x, v0.y, v0.z, v0.w};
            float a1[4] = {v1.x, v1.y, v1.z, v1.w};
            #pragma unroll
            for (int j = 0; j < 4; j++) {
                int c = c4 * 4 + j;
                int ntv = c >> 3, gnv = c & 7;
                vimg[ntv * 256 + gnv * 16 + koff] = pack_bf16(a0[j], a1[j]);
            }
        } else {
            vimg[12 * 256 + 0 + koff] = pack_bf16(j0 < NTOK ? 1.f : 0.f,
                                                  j1 < NTOK ? 1.f : 0.f);
            #pragma unroll
            for (int gnv = 1; gnv < 8; gnv++)
                vimg[12 * 256 + gnv * 16 + koff] = 0u;
        }
    }
    // packed bias indices (head-independent)
    if (head == 0 && tid < 64) {
        int kg = tile * 64 + tid;
        int packed;
        if (kg >= NTOK) packed = -1;
        else if (kg == 0) packed = 64 | (65 << 8) | (66 << 16);
        else {
            int ss = kg - 1;
            int t = ss / 784; int rr2 = ss - t * 784;
            int hh = rr2 / 28; int ww = rr2 - hh * 28;
            packed = t | ((8 + hh) << 8) | ((36 + ww) << 16);
        }
        g_ki[tile * 64 + tid] = packed;
    }
}

// ---------------------------------------------------------------------------
// Flash attention v8: cp.async staging from prebuilt images; register Q;
// fixed-shift softmax + ones-column l. grid (66,2), block 384.
// ---------------------------------------------------------------------------
#define SQ_OFF  0        // 6 mt * 6 kt * 128 = 4608 words
#define SK_OFF  4608     // 2 buf * 3072
#define SV_OFF  10752    // 2 buf * 3328
#define SB_OFF  17408    // 96 * 68 = 6528
#define SKI_OFF 23936    // 2 buf * 64 ints
#define FLASH_SMEM (24064 * 4)
#define OSTR 100

__device__ __forceinline__ void cp_stage(unsigned sbyte, int head, int t, int buf, int tid)
{
    const uint4* ks = (const uint4*)(g_kimg + (head * NT_TILES + t) * 3072);
    unsigned kd = sbyte + (SK_OFF + buf * 3072) * 4;
    for (int i = tid; i < 768; i += 384) cp16(kd + i * 16, ks + i);
    const uint4* vs = (const uint4*)(g_vimg + (head * NT_TILES + t) * 3328);
    unsigned vd = sbyte + (SV_OFF + buf * 3328) * 4;
    for (int i = tid; i < 832; i += 384) cp16(vd + i * 16, vs + i);
    if (tid < 16) {
        const uint4* is_ = (const uint4*)(g_ki + t * 64);
        unsigned idd = sbyte + (SKI_OFF + buf * 64) * 4;
        cp16(idd + tid * 16, is_ + tid);
    }
}

__global__ __launch_bounds__(384, 1) void flash_mma_kernel()
{
    extern __shared__ float sm[];
    float* sQp = sm + SQ_OFF;
    float* sB  = sm + SB_OFF;
    unsigned sbyte = smem_u32(sm);

    const int head = blockIdx.y;
    const int q0 = blockIdx.x * 96;
    const int tid = threadIdx.x;
    const int lane = tid & 31, warp = tid >> 5;
    const int mw = warp >> 1, nw = warp & 1;

    const float* qp = g_pool + head * NTOK * HD_;

    // kick off tile 0 copies
    cp_stage(sbyte, head, 0, 0, tid);
    CP_COMMIT();

    // Q -> bf16 A-fragment layout (staged once, then hoisted to registers)
    {
        int r_g = tid >> 2;
        int row = q0 + r_g;
        bool ok = row < NTOK;
        int mt = r_g >> 4, r = r_g & 15;
        int rh = (r >> 3) & 1;
        #pragma unroll
        for (int c4 = tid & 3; c4 < 24; c4 += 4) {
            float4 v = ok ? *(const float4*)(qp + row * 96 + c4 * 4)
                          : make_float4(0.f, 0.f, 0.f, 0.f);
            int p0 = 2 * c4;
            int kt = p0 >> 3, p = p0 & 7;
            unsigned* dst = (unsigned*)sQp + (mt * 6 + kt) * 128;
            dst[((r & 7) * 4 + (p & 3)) * 4 + rh + 2 * (p >> 2)]   = pack_bf16(v.x, v.y);
            int p1 = p + 1;
            dst[((r & 7) * 4 + (p1 & 3)) * 4 + rh + 2 * (p1 >> 2)] = pack_bf16(v.z, v.w);
        }
    }
    // bias rows
    for (int idx = tid; idx < 96 * 17; idx += 384) {
        int r = idx / 17, c4 = idx - r * 17;
        int row = q0 + r; if (row >= NTOK) row = NTOK - 1;
        *(float4*)(sB + r * 68 + c4 * 4) =
            *(const float4*)(g_bias + (head * NTOK + row) * BROW + c4 * 4);
    }
    CP_WAIT0();
    __syncthreads();

    // hoist Q fragments (tile-invariant)
    float4 aq[6];
    #pragma unroll
    for (int kt = 0; kt < 6; kt++)
        aq[kt] = *(const float4*)(sQp + ((mw * 6 + kt) * 32 + lane) * 4);

    float oacc[13][4] = {};
    const int rloc = mw * 16 + (lane >> 2);
    const float* Br0 = sB + rloc * 68;
    const float* Br1 = Br0 + 8 * 68;

    for (int t = 0; t < NT_TILES; t++) {
        int buf = t & 1;
        if (t + 1 < NT_TILES) {
            cp_stage(sbyte, head, t + 1, buf ^ 1, tid);
            CP_COMMIT();
        }

        float* sKb = sm + SK_OFF + buf * 3072;
        float* sVb = sm + SV_OFF + buf * 3328;
        int*   sKIb = (int*)(sm + SKI_OFF) + buf * 64;

        // S = Q K^T over this warp's key half (Q from registers)
        float d[4][4] = {};
        #pragma unroll
        for (int kt = 0; kt < 6; kt++) {
            #pragma unroll
            for (int nt = 0; nt < 4; nt++) {
                float2 b = *(const float2*)(sKb + (((nw * 4 + nt) * 6 + kt) * 32 + lane) * 2);
                mma16(d[nt], aq[kt], b);
            }
        }

        // scale + bias + mask, then p = exp2(d) (fixed-shift softmax)
        unsigned pk[2][4];
        #pragma unroll
        for (int nt = 0; nt < 4; nt++) {
            int c0 = nw * 32 + nt * 8 + (lane & 3) * 2;
            int p0 = sKIb[c0], p1 = sKIb[c0 + 1];
            if (p0 >= 0) {
                int i0 = p0 & 255, i1 = (p0 >> 8) & 255, i2 = p0 >> 16;
                d[nt][0] = d[nt][0] * SCL2 + (Br0[i0] + Br0[i1] + Br0[i2]);
                d[nt][2] = d[nt][2] * SCL2 + (Br1[i0] + Br1[i1] + Br1[i2]);
            } else { d[nt][0] = -1e30f; d[nt][2] = -1e30f; }
            if (p1 >= 0) {
                int i0 = p1 & 255, i1 = (p1 >> 8) & 255, i2 = p1 >> 16;
                d[nt][1] = d[nt][1] * SCL2 + (Br0[i0] + Br0[i1] + Br0[i2]);
                d[nt][3] = d[nt][3] * SCL2 + (Br1[i0] + Br1[i1] + Br1[i2]);
            } else { d[nt][1] = -1e30f; d[nt][3] = -1e30f; }
            float p00 = fexp2(d[nt][0]), p01 = fexp2(d[nt][1]);
            float p10 = fexp2(d[nt][2]), p11 = fexp2(d[nt][3]);
            pk[nt >> 1][(nt & 1) * 2 + 0] = pack_bf16(p00, p01);
            pk[nt >> 1][(nt & 1) * 2 + 1] = pack_bf16(p10, p11);
        }

        // O += P V  (paired LDS.128 covers both k16 fragments; 13th nt = l)
        float4 af0 = make_float4(__uint_as_float(pk[0][0]), __uint_as_float(pk[0][1]),
                                 __uint_as_float(pk[0][2]), __uint_as_float(pk[0][3]));
        float4 af1 = make_float4(__uint_as_float(pk[1][0]), __uint_as_float(pk[1][1]),
                                 __uint_as_float(pk[1][2]), __uint_as_float(pk[1][3]));
        #pragma unroll
        for (int nt = 0; nt < 13; nt++) {
            float4 b4 = *(const float4*)(sVb + (nt * 2 + nw) * 128 + lane * 4);
            mma16(oacc[nt], af0, make_float2(b4.x, b4.y));
            mma16(oacc[nt], af1, make_float2(b4.z, b4.w));
        }

        if (t + 1 < NT_TILES) {
            CP_WAIT0();
            __syncthreads();
        }
    }

    // extract l (ones channel, col 96), combine split-KV halves
    float lA = __shfl_sync(0xffffffffu, oacc[12][0], lane & 28);
    float lB = __shfl_sync(0xffffffffu, oacc[12][2], lane & 28);

    __syncthreads();
    float* sO  = sm;                 // 96 * OSTR
    float* sLl = sm + 96 * OSTR;     // 96
    int g = lane >> 2, tq = lane & 3;
    int rl0 = mw * 16 + g, rl1 = rl0 + 8;

    if (nw == 1) {
        #pragma unroll
        for (int nt = 0; nt < 12; nt++) {
            *(float2*)(sO + rl0 * OSTR + nt * 8 + tq * 2) = make_float2(oacc[nt][0], oacc[nt][1]);
            *(float2*)(sO + rl1 * OSTR + nt * 8 + tq * 2) = make_float2(oacc[nt][2], oacc[nt][3]);
        }
        if (tq == 0) { sLl[rl0] = lA; sLl[rl1] = lB; }
    }
    __syncthreads();
    if (nw == 0) {
        float inv0 = 1.f / (lA + sLl[rl0]);
        float inv1 = 1.f / (lB + sLl[rl1]);
        int r0 = q0 + rl0, r1 = q0 + rl1;
        #pragma unroll
        for (int nt = 0; nt < 12; nt++) {
            int c = nt * 8 + tq * 2;
            if (r0 < NTOK) {
                float2 o1 = *(float2*)(sO + rl0 * OSTR + c);
                float x0 = (oacc[nt][0] + o1.x) * inv0;
                float x1 = (oacc[nt][1] + o1.y) * inv0;
                if (r0 >= 1) { x0 += qp[r0 * 96 + c]; x1 += qp[r0 * 96 + c + 1]; }
                g_att[r0 * 192 + head * 96 + c]     = x0;
                g_att[r0 * 192 + head * 96 + c + 1] = x1;
            }
            if (r1 < NTOK) {
                float2 o1 = *(float2*)(sO + rl1 * OSTR + c);
                float x0 = (oacc[nt][2] + o1.x) * inv1;
                float x1 = (oacc[nt][3] + o1.y) * inv1;
                x0 += qp[r1 * 96 + c]; x1 += qp[r1 * 96 + c + 1];
                g_att[r1 * 192 + head * 96 + c]     = x0;
                g_att[r1 * 192 + head * 96 + c + 1] = x1;
            }
        }
    }
}

// ---------------------------------------------------------------------------
extern "C" void kernel_launch(void* const* d_in, const int* in_sizes, int n_in,
                              void* d_out, int out_size)
{
    const float* x      = (const float*)d_in[0];
    const float* qkv_w  = (const float*)d_in[1];
    const float* qkv_b  = (const float*)d_in[2];
    const float* proj_w = (const float*)d_in[3];
    const float* proj_b = (const float*)d_in[4];
    const float* pqw    = (const float*)d_in[5];
    const float* pkw    = (const float*)d_in[6];
    const float* pvw    = (const float*)d_in[7];
    const float* nqg    = (const float*)d_in[8];
    const float* nqb    = (const float*)d_in[9];
    const float* nkg    = (const float*)d_in[10];
    const float* nkb    = (const float*)d_in[11];
    const float* nvg    = (const float*)d_in[12];
    const float* nvb    = (const float*)d_in[13];
    const float* rel_h  = (const float*)d_in[14];
    const float* rel_w  = (const float*)d_in[15];
    const float* rel_t  = (const float*)d_in[16];
    float* out = (float*)d_out;

    const int smem_bias = (125 * RSTRIDE + 128 * 96) * 4;
    cudaFuncSetAttribute(flash_mma_kernel, cudaFuncAttributeMaxDynamicSharedMemorySize, FLASH_SMEM);
    cudaFuncSetAttribute(bias_kernel, cudaFuncAttributeMaxDynamicSharedMemorySize, smem_bias);

    dim3 g1(99, 9);
    gemm_mma_kernel<<<g1, 256>>>(x, qkv_w, qkv_b, nullptr, NTOK, 576, 0);

    dim3 g2(785, 6);
    pool_kernel<<<g2, 256>>>(pqw, pkw, pvw, nqg, nqb, nkg, nkb, nvg, nvb);

    dim3 g3(49, 2);
    bias_kernel<<<g3, 256, smem_bias>>>(rel_h, rel_w, rel_t);

    dim3 gp(NT_TILES, 2);
    prep_kernel<<<gp, 256>>>();

    dim3 g4(66, 2);
    flash_mma_kernel<<<g4, 384, FLASH_SMEM>>>();

    dim3 g5(99, 3);
    gemm_mma_kernel<<<g5, 256>>>(nullptr, proj_w, proj_b, out, NTOK, 192, 1);
}

// round 15
// speedup vs baseline: 2.1055x; 1.0909x over previous
#include <cuda_runtime.h>
#include <cuda_bf16.h>
#include <cstdint>
#include <math.h>

#define T_    8
#define H_    28
#define W_    28
#define SP_   6272
#define NTOK  6273
#define DIM_  192
#define HD_   96
#define BROW  68
#define SCALE_ 0.1020620726159658f   // 96^-0.5
#define LOG2E  1.4426950408889634f
#define SCL2   (SCALE_ * LOG2E)
#define NT_TILES 99
#define NKT 10

// Scratch (static device memory — no allocations)
__device__ float g_raw [6 * NTOK * HD_];
__device__ float g_pool[6 * NTOK * HD_];
__device__ float g_bias[2 * NTOK * BROW];
__device__ float g_att [NTOK * DIM_];
__device__ unsigned g_kimg[2 * NT_TILES * 5120];  // K_ext fragment-layout images (160ch)
__device__ unsigned g_vimg[2 * NT_TILES * 3328];  // V fragment-layout images (paired)

// ---------------------------------------------------------------------------
__device__ __forceinline__ float cvt_tf32(float x) {
    unsigned u; asm("cvt.rna.tf32.f32 %0, %1;" : "=r"(u) : "f"(x));
    return __uint_as_float(u);
}
__device__ __forceinline__ float fexp2(float x) {
    float y; asm("ex2.approx.ftz.f32 %0, %1;" : "=f"(y) : "f"(x)); return y;
}
__device__ __forceinline__ unsigned pack_bf16(float x, float y) {
    __nv_bfloat162 h = __float22bfloat162_rn(make_float2(x, y));
    return *(unsigned*)&h;
}
__device__ __forceinline__ void mma8(float* d, const float4& a, const float2& b) {
    asm volatile("mma.sync.aligned.m16n8k8.row.col.f32.tf32.tf32.f32 "
        "{%0,%1,%2,%3}, {%4,%5,%6,%7}, {%8,%9}, {%0,%1,%2,%3};"
        : "+f"(d[0]), "+f"(d[1]), "+f"(d[2]), "+f"(d[3])
        : "r"(__float_as_uint(a.x)), "r"(__float_as_uint(a.y)),
          "r"(__float_as_uint(a.z)), "r"(__float_as_uint(a.w)),
          "r"(__float_as_uint(b.x)), "r"(__float_as_uint(b.y)));
}
__device__ __forceinline__ void mma16(float* d, const float4& a, const float2& b) {
    asm volatile("mma.sync.aligned.m16n8k16.row.col.f32.bf16.bf16.f32 "
        "{%0,%1,%2,%3}, {%4,%5,%6,%7}, {%8,%9}, {%0,%1,%2,%3};"
        : "+f"(d[0]), "+f"(d[1]), "+f"(d[2]), "+f"(d[3])
        : "r"(__float_as_uint(a.x)), "r"(__float_as_uint(a.y)),
          "r"(__float_as_uint(a.z)), "r"(__float_as_uint(a.w)),
          "r"(__float_as_uint(b.x)), "r"(__float_as_uint(b.y)));
}
__device__ __forceinline__ unsigned smem_u32(const void* p) {
    unsigned a;
    asm("{ .reg .u64 t; cvta.to.shared.u64 t, %1; cvt.u32.u64 %0, t; }" : "=r"(a) : "l"(p));
    return a;
}
__device__ __forceinline__ void cp16(unsigned s, const void* g) {
    asm volatile("cp.async.cg.shared.global [%0], [%1], 16;" :: "r"(s), "l"(g) : "memory");
}
#define CP_COMMIT() asm volatile("cp.async.commit_group;" ::: "memory")
#define CP_WAIT0()  asm volatile("cp.async.wait_group 0;" ::: "memory")

// ---------------------------------------------------------------------------
// tf32 mma GEMM  (unchanged, known-good)
// ---------------------------------------------------------------------------
__global__ __launch_bounds__(256) void gemm_mma_kernel(
    const float* __restrict__ A, const float* __restrict__ Bm,
    const float* __restrict__ bias, float* __restrict__ out,
    int M, int N, int mode)
{
    __shared__ float sA[6144];
    __shared__ float sB[6144];
    const float* Ap = (mode == 1) ? g_att : A;

    int tid = threadIdx.x, lane = tid & 31, warp = tid >> 5;
    int mw = warp >> 1, nh = warp & 1;
    int m0 = blockIdx.x * 64, n0 = blockIdx.y * 64;

    float d[4][4] = {};

    for (int k0 = 0; k0 < 192; k0 += 96) {
        __syncthreads();
        {
            int r_g = tid >> 2, r = r_g & 15, mt = r_g >> 4;
            int row = m0 + r_g; if (row >= M) row = M - 1;
            #pragma unroll
            for (int c4 = tid & 3; c4 < 24; c4 += 4) {
                float4 v = *(const float4*)(Ap + row * 192 + k0 + c4 * 4);
                int base = (mt * 12 + (c4 >> 1)) * 128 + (r & 7) * 16
                           + ((r >> 3) & 1) + 2 * (c4 & 1);
                sA[base + 0]  = cvt_tf32(v.x); sA[base + 4]  = cvt_tf32(v.y);
                sA[base + 8]  = cvt_tf32(v.z); sA[base + 12] = cvt_tf32(v.w);
            }
        }
        {
            int r_g = tid >> 2;
            int nt = r_g >> 3, gn = r_g & 7;
            #pragma unroll
            for (int c4 = tid & 3; c4 < 24; c4 += 4) {
                float4 v = *(const float4*)(Bm + (n0 + r_g) * 192 + k0 + c4 * 4);
                int base = (nt * 12 + (c4 >> 1)) * 64 + gn * 8 + (c4 & 1);
                sB[base + 0] = cvt_tf32(v.x); sB[base + 2] = cvt_tf32(v.y);
                sB[base + 4] = cvt_tf32(v.z); sB[base + 6] = cvt_tf32(v.w);
            }
        }
        __syncthreads();
        #pragma unroll
        for (int kt = 0; kt < 12; kt++) {
            float4 a = *(const float4*)(sA + ((mw * 12 + kt) * 32 + lane) * 4);
            #pragma unroll
            for (int nt = 0; nt < 4; nt++) {
                float2 b = *(const float2*)(sB + (((nh * 4 + nt) * 12 + kt) * 32 + lane) * 2);
                mma8(d[nt], a, b);
            }
        }
    }

    int g = lane >> 2, tq = lane & 3;
    int r0 = m0 + mw * 16 + g, r1 = r0 + 8;
    #pragma unroll
    for (int nt = 0; nt < 4; nt++) {
        int col = n0 + nh * 32 + nt * 8 + tq * 2;
        #pragma unroll
        for (int e = 0; e < 2; e++) {
            int c = col + e;
            float b = bias[c];
            float v0 = d[nt][e]     + b;
            float v1 = d[nt][e + 2] + b;
            if (mode == 0) {
                int which = c / DIM_;
                int rem   = c - which * DIM_;
                int head  = rem / HD_;
                int cc    = rem - head * HD_;
                int base  = (which * 2 + head) * NTOK * HD_ + cc;
                if (r0 < M) g_raw[base + r0 * HD_] = v0;
                if (r1 < M) g_raw[base + r1 * HD_] = v1;
            } else {
                if (r0 < M) out[r0 * N + c] = v0;
                if (r1 < M) out[r1 * N + c] = v1;
            }
        }
    }
}

// ---------------------------------------------------------------------------
// Attention pool (unchanged): 1 warp/token, smem weights, shuffle LN
// ---------------------------------------------------------------------------
__global__ __launch_bounds__(256) void pool_kernel(
    const float* __restrict__ wq, const float* __restrict__ wk, const float* __restrict__ wv,
    const float* __restrict__ gq, const float* __restrict__ bq,
    const float* __restrict__ gk, const float* __restrict__ bk,
    const float* __restrict__ gv, const float* __restrict__ bv)
{
    __shared__ float sW[27 * 96];
    int tid = threadIdx.x;
    int yy  = blockIdx.y;
    int tensor = yy >> 1, head = yy & 1;

    const float* wc = (tensor == 0) ? wq : (tensor == 1) ? wk : wv;
    const float* g  = (tensor == 0) ? gq : (tensor == 1) ? gk : gv;
    const float* b  = (tensor == 0) ? bq : (tensor == 1) ? bk : bv;

    for (int i = tid; i < 27 * 96; i += 256) {
        int tap = i / 96, c = i - tap * 96;
        sW[i] = wc[c * 27 + tap];
    }
    __syncthreads();

    int w = tid >> 5, lane = tid & 31;
    int tok = blockIdx.x * 8 + w;
    if (tok < NTOK) {
        const float* in = g_raw + (tensor * 2 + head) * NTOK * HD_;
        float v0, v1, v2;
        if (tok == 0) {
            v0 = in[lane]; v1 = in[lane + 32]; v2 = in[lane + 64];
        } else {
            int s = tok - 1;
            int t = s / 784; int r = s - t * 784;
            int h = r / 28;  int ww = r - h * 28;
            v0 = v1 = v2 = 0.f;
            #pragma unroll
            for (int dt = -1; dt <= 1; dt++) {
                int tt = t + dt; if ((unsigned)tt >= (unsigned)T_) continue;
                #pragma unroll
                for (int dh = -1; dh <= 1; dh++) {
                    int hh = h + dh; if ((unsigned)hh >= (unsigned)H_) continue;
                    #pragma unroll
                    for (int dw = -1; dw <= 1; dw++) {
                        int w2 = ww + dw; if ((unsigned)w2 >= (unsigned)W_) continue;
                        int nb = 1 + (tt * 28 + hh) * 28 + w2;
                        int tap = (dt + 1) * 9 + (dh + 1) * 3 + (dw + 1);
                        const float* p  = in + nb * 96;
                        const float* wr = sW + tap * 96;
                        v0 += p[lane]      * wr[lane];
                        v1 += p[lane + 32] * wr[lane + 32];
                        v2 += p[lane + 64] * wr[lane + 64];
                    }
                }
            }
        }
        float s1 = v0 + v1 + v2;
        float s2 = v0 * v0 + v1 * v1 + v2 * v2;
        #pragma unroll
        for (int o = 1; o < 32; o <<= 1) {
            s1 += __shfl_xor_sync(0xffffffffu, s1, o);
            s2 += __shfl_xor_sync(0xffffffffu, s2, o);
        }
        float mean = s1 * (1.f / 96.f);
        float var  = s2 * (1.f / 96.f) - mean * mean;
        float is   = rsqrtf(var + 1e-5f);
        float* outp = g_pool + (tensor * 2 + head) * NTOK * HD_ + tok * 96;
        outp[lane]      = (v0 - mean) * is * g[lane]      + b[lane];
        outp[lane + 32] = (v1 - mean) * is * g[lane + 32] + b[lane + 32];
        outp[lane + 64] = (v2 - mean) * is * g[lane + 64] + b[lane + 64];
    }
}

// ---------------------------------------------------------------------------
// Rel-bias precompute (unchanged; output ×LOG2E)
#define RSTRIDE 100
__global__ __launch_bounds__(256) void bias_kernel(
    const float* __restrict__ rel_h, const float* __restrict__ rel_w,
    const float* __restrict__ rel_t)
{
    extern __shared__ float bsm[];
    float* sRel = bsm;
    float* sQ   = bsm + 125 * RSTRIDE;
    int head = blockIdx.y;
    int qb = blockIdx.x * 128;
    int tid = threadIdx.x;
    const float* qp = g_pool + head * NTOK * HD_;

    if (blockIdx.x == 0 && tid < BROW)
        g_bias[(head * NTOK) * BROW + tid] = 0.f;

    for (int idx = tid; idx < 125 * 24; idx += 256) {
        int row = idx / 24, c4 = idx - row * 24;
        const float* src = row < 15 ? rel_t + row * 96
                         : row < 70 ? rel_h + (row - 15) * 96
                                    : rel_w + (row - 70) * 96;
        float4 v = *(const float4*)(src + c4 * 4);
        float* dst = sRel + row * RSTRIDE + c4 * 4;
        dst[0] = v.x * LOG2E; dst[1] = v.y * LOG2E;
        dst[2] = v.z * LOG2E; dst[3] = v.w * LOG2E;
    }
    for (int idx = tid; idx < 128 * 24; idx += 256) {
        int r = idx / 24, c4 = idx - r * 24;
        *(float4*)(sQ + r * 96 + c4 * 4) =
            *(const float4*)(qp + (qb + 1 + r) * 96 + c4 * 4);
    }
    __syncthreads();

    for (int it = tid; it < 128 * 64; it += 256) {
        int ql = it >> 6, i = it & 63;
        int s = qb + ql;
        int t = s / 784; int rr = s - t * 784;
        int h = rr / 28; int w = rr - h * 28;
        int row = (i < 8)  ? (t - i + 7)
                : (i < 36) ? 15 + (h - (i - 8) + 27)
                           : 70 + (w - (i - 36) + 27);
        const float* q4 = sQ + ql * 96;
        const float* r4 = sRel + row * RSTRIDE;
        float sum = 0.f;
        #pragma unroll
        for (int c = 0; c < 96; c += 4) {
            float4 a = *(const float4*)(q4 + c);
            float4 b = *(const float4*)(r4 + c);
            sum += a.x*b.x + a.y*b.y + a.z*b.z + a.w*b.w;
        }
        g_bias[(head * NTOK + s + 1) * BROW + i] = sum;
    }
    for (int idx = tid; idx < 128 * 4; idx += 256) {
        int ql = idx >> 2, i = 64 + (idx & 3);
        g_bias[(head * NTOK + qb + 1 + ql) * BROW + i] = 0.f;
    }
}

// ---------------------------------------------------------------------------
// Prep: build K_ext (160ch: SCL2*k + 3-hot) and V fragment-layout images.
// grid (99, 2), 256 threads.
// ---------------------------------------------------------------------------
__global__ __launch_bounds__(256) void prep_kernel()
{
    int tile = blockIdx.x, head = blockIdx.y;
    int tid = threadIdx.x;
    unsigned* kimg = g_kimg + (head * NT_TILES + tile) * 5120;
    unsigned* vimg = g_vimg + (head * NT_TILES + tile) * 3328;
    const float* kp = g_pool + (2 + head) * NTOK * HD_;
    const float* vp = g_pool + (4 + head) * NTOK * HD_;

    // K_ext: 64 keys x 40 c4-chunks -> B-fragment layout words (10 k16 steps)
    for (int idx = tid; idx < 2560; idx += 256) {
        int r = idx / 40, c4 = idx - r * 40;
        int rowg = tile * 64 + r;
        float4 kv = make_float4(0.f, 0.f, 0.f, 0.f);
        if (rowg < NTOK) {
            if (c4 < 24) {
                const float* s = kp + rowg * 96 + c4 * 4;
                kv = make_float4(s[0] * SCL2, s[1] * SCL2, s[2] * SCL2, s[3] * SCL2);
            } else if (rowg > 0) {
                int ss = rowg - 1;
                int t = ss / 784; int rr = ss - t * 784;
                int hh = rr / 28; int ww = rr - hh * 28;
                int i0 = t, i1 = 8 + hh, i2 = 36 + ww;
                int base = (c4 - 24) * 4;
                float* a = &kv.x;
                #pragma unroll
                for (int e = 0; e < 4; e++) {
                    int pos = base + e;
                    if (pos == i0 || pos == i1 || pos == i2) a[e] = 1.f;
                }
            }
        }
        int ntk = r >> 3, gnk = r & 7;
        int p0 = 2 * c4;
        int kt = p0 >> 3, p = p0 & 7;
        unsigned* dK = kimg + (ntk * NKT + kt) * 64;
        dK[(gnk * 4 + (p & 3)) * 2 + (p >> 2)]   = pack_bf16(kv.x, kv.y);
        int p1 = p + 1;
        dK[(gnk * 4 + (p1 & 3)) * 2 + (p1 >> 2)] = pack_bf16(kv.z, kv.w);
    }
    // V: 32 key-pairs x 25 c4-chunks -> paired B-fragment layout
    for (int idx = tid; idx < 800; idx += 256) {
        int jp = idx / 25, c4 = idx - jp * 25;
        int j0 = tile * 64 + 2 * jp, j1 = j0 + 1;
        int ktv = jp >> 3, pv = jp & 7;
        int koff = (ktv >> 1) * 128 + (pv & 3) * 4 + (ktv & 1) * 2 + (pv >> 2);
        if (c4 < 24) {
            float4 v0 = (j0 < NTOK) ? *(const float4*)(vp + j0 * 96 + c4 * 4)
                                    : make_float4(0.f, 0.f, 0.f, 0.f);
            float4 v1 = (j1 < NTOK) ? *(const float4*)(vp + j1 * 96 + c4 * 4)
                                    : make_float4(0.f, 0.f, 0.f, 0.f);
            float a0[4] = {v0.x, v0.y, v0.z, v0.w};
            float a1[4] = {v1.x, v1.y, v1.z, v1.w};
            #pragma unroll
            for (int j = 0; j < 4; j++) {
                int c = c4 * 4 + j;
                int ntv = c >> 3, gnv = c & 7;
                vimg[ntv * 256 + gnv * 16 + koff] = pack_bf16(a0[j], a1[j]);
            }
        } else {
            vimg[12 * 256 + 0 + koff] = pack_bf16(j0 < NTOK ? 1.f : 0.f,
                                                  j1 < NTOK ? 1.f : 0.f);
            #pragma unroll
            for (int gnv = 1; gnv < 8; gnv++)
                vimg[12 * 256 + gnv * 16 + koff] = 0u;
        }
    }
}

// ---------------------------------------------------------------------------
// Flash attention v9: bias folded into 160-dim S-mma; cp.async staging from
// prebuilt images; register Q_ext; fixed-shift softmax + ones-column l.
// grid (66,2), block 384.
// ---------------------------------------------------------------------------
#define SQ_OFF  0        // 6 mt * 10 kt * 128 = 7680 words
#define SK_OFF  7680     // 2 buf * 5120
#define SV_OFF  17920    // 2 buf * 3328
#define FLASH_SMEM (24576 * 4)
#define OSTR 100

__device__ __forceinline__ void cp_stage(unsigned sbyte, int head, int t, int buf, int tid)
{
    const uint4* ks = (const uint4*)(g_kimg + (head * NT_TILES + t) * 5120);
    unsigned kd = sbyte + (SK_OFF + buf * 5120) * 4;
    for (int i = tid; i < 1280; i += 384) cp16(kd + i * 16, ks + i);
    const uint4* vs = (const uint4*)(g_vimg + (head * NT_TILES + t) * 3328);
    unsigned vd = sbyte + (SV_OFF + buf * 3328) * 4;
    for (int i = tid; i < 832; i += 384) cp16(vd + i * 16, vs + i);
}

__global__ __launch_bounds__(384, 1) void flash_mma_kernel()
{
    extern __shared__ float sm[];
    float* sQp = sm + SQ_OFF;
    unsigned sbyte = smem_u32(sm);

    const int head = blockIdx.y;
    const int q0 = blockIdx.x * 96;
    const int tid = threadIdx.x;
    const int lane = tid & 31, warp = tid >> 5;
    const int mw = warp >> 1, nw = warp & 1;

    const float* qp = g_pool + head * NTOK * HD_;

    // kick off tile 0 copies
    cp_stage(sbyte, head, 0, 0, tid);
    CP_COMMIT();

    // Q_ext = [q (96), bias row ×LOG2E (64)] -> bf16 A-fragment layout
    {
        int r_g = tid >> 2;
        int row = q0 + r_g;
        bool ok = row < NTOK;
        int mt = r_g >> 4, r = r_g & 15;
        int rh = (r >> 3) & 1;
        const float* brow = g_bias + (head * NTOK + (ok ? row : 0)) * BROW;
        #pragma unroll
        for (int c4 = tid & 3; c4 < 40; c4 += 4) {
            float4 v = make_float4(0.f, 0.f, 0.f, 0.f);
            if (ok) {
                v = (c4 < 24) ? *(const float4*)(qp + row * 96 + c4 * 4)
                              : *(const float4*)(brow + (c4 - 24) * 4);
            }
            int p0 = 2 * c4;
            int kt = p0 >> 3, p = p0 & 7;
            unsigned* dst = (unsigned*)sQp + (mt * NKT + kt) * 128;
            dst[((r & 7) * 4 + (p & 3)) * 4 + rh + 2 * (p >> 2)]   = pack_bf16(v.x, v.y);
            int p1 = p + 1;
            dst[((r & 7) * 4 + (p1 & 3)) * 4 + rh + 2 * (p1 >> 2)] = pack_bf16(v.z, v.w);
        }
    }
    CP_WAIT0();
    __syncthreads();

    // hoist Q_ext fragments (tile-invariant)
    float4 aq[NKT];
    #pragma unroll
    for (int kt = 0; kt < NKT; kt++)
        aq[kt] = *(const float4*)(sQp + ((mw * NKT + kt) * 32 + lane) * 4);

    float oacc[13][4] = {};

    for (int t = 0; t < NT_TILES; t++) {
        int buf = t & 1;
        if (t + 1 < NT_TILES) {
            cp_stage(sbyte, head, t + 1, buf ^ 1, tid);
            CP_COMMIT();
        }

        float* sKb = sm + SK_OFF + buf * 5120;
        float* sVb = sm + SV_OFF + buf * 3328;

        // S_log2 = Q_ext K_ext^T (scale+bias inside the mma)
        float d[4][4] = {};
        #pragma unroll
        for (int kt = 0; kt < NKT; kt++) {
            #pragma unroll
            for (int nt = 0; nt < 4; nt++) {
                float2 b = *(const float2*)(sKb + (((nw * 4 + nt) * NKT + kt) * 32 + lane) * 2);
                mma16(d[nt], aq[kt], b);
            }
        }

        // p = exp2(d)  (fixed-shift softmax; no mask needed)
        unsigned pk[2][4];
        #pragma unroll
        for (int nt = 0; nt < 4; nt++) {
            pk[nt >> 1][(nt & 1) * 2 + 0] = pack_bf16(fexp2(d[nt][0]), fexp2(d[nt][1]));
            pk[nt >> 1][(nt & 1) * 2 + 1] = pack_bf16(fexp2(d[nt][2]), fexp2(d[nt][3]));
        }

        // O += P V  (paired LDS.128; 13th nt = l via ones column)
        float4 af0 = make_float4(__uint_as_float(pk[0][0]), __uint_as_float(pk[0][1]),
                                 __uint_as_float(pk[0][2]), __uint_as_float(pk[0][3]));
        float4 af1 = make_float4(__uint_as_float(pk[1][0]), __uint_as_float(pk[1][1]),
                                 __uint_as_float(pk[1][2]), __uint_as_float(pk[1][3]));
        #pragma unroll
        for (int nt = 0; nt < 13; nt++) {
            float4 b4 = *(const float4*)(sVb + (nt * 2 + nw) * 128 + lane * 4);
            mma16(oacc[nt], af0, make_float2(b4.x, b4.y));
            mma16(oacc[nt], af1, make_float2(b4.z, b4.w));
        }

        if (t + 1 < NT_TILES) {
            CP_WAIT0();
            __syncthreads();
        }
    }

    // extract l (ones channel, col 96), combine split-KV halves
    float lA = __shfl_sync(0xffffffffu, oacc[12][0], lane & 28);
    float lB = __shfl_sync(0xffffffffu, oacc[12][2], lane & 28);

    __syncthreads();
    float* sO  = sm;                 // 96 * OSTR
    float* sLl = sm + 96 * OSTR;     // 96
    int g = lane >> 2, tq = lane & 3;
    int rl0 = mw * 16 + g, rl1 = rl0 + 8;

    if (nw == 1) {
        #pragma unroll
        for (int nt = 0; nt < 12; nt++) {
            *(float2*)(sO + rl0 * OSTR + nt * 8 + tq * 2) = make_float2(oacc[nt][0], oacc[nt][1]);
            *(float2*)(sO + rl1 * OSTR + nt * 8 + tq * 2) = make_float2(oacc[nt][2], oacc[nt][3]);
        }
        if (tq == 0) { sLl[rl0] = lA; sLl[rl1] = lB; }
    }
    __syncthreads();
    if (nw == 0) {
        float inv0 = 1.f / (lA + sLl[rl0]);
        float inv1 = 1.f / (lB + sLl[rl1]);
        int r0 = q0 + rl0, r1 = q0 + rl1;
        #pragma unroll
        for (int nt = 0; nt < 12; nt++) {
            int c = nt * 8 + tq * 2;
            if (r0 < NTOK) {
                float2 o1 = *(float2*)(sO + rl0 * OSTR + c);
                float x0 = (oacc[nt][0] + o1.x) * inv0;
                float x1 = (oacc[nt][1] + o1.y) * inv0;
                if (r0 >= 1) { x0 += qp[r0 * 96 + c]; x1 += qp[r0 * 96 + c + 1]; }
                g_att[r0 * 192 + head * 96 + c]     = x0;
                g_att[r0 * 192 + head * 96 + c + 1] = x1;
            }
            if (r1 < NTOK) {
                float2 o1 = *(float2*)(sO + rl1 * OSTR + c);
                float x0 = (oacc[nt][2] + o1.x) * inv1;
                float x1 = (oacc[nt][3] + o1.y) * inv1;
                x0 += qp[r1 * 96 + c]; x1 += qp[r1 * 96 + c + 1];
                g_att[r1 * 192 + head * 96 + c]     = x0;
                g_att[r1 * 192 + head * 96 + c + 1] = x1;
            }
        }
    }
}

// ---------------------------------------------------------------------------
extern "C" void kernel_launch(void* const* d_in, const int* in_sizes, int n_in,
                              void* d_out, int out_size)
{
    const float* x      = (const float*)d_in[0];
    const float* qkv_w  = (const float*)d_in[1];
    const float* qkv_b  = (const float*)d_in[2];
    const float* proj_w = (const float*)d_in[3];
    const float* proj_b = (const float*)d_in[4];
    const float* pqw    = (const float*)d_in[5];
    const float* pkw    = (const float*)d_in[6];
    const float* pvw    = (const float*)d_in[7];
    const float* nqg    = (const float*)d_in[8];
    const float* nqb    = (const float*)d_in[9];
    const float* nkg    = (const float*)d_in[10];
    const float* nkb    = (const float*)d_in[11];
    const float* nvg    = (const float*)d_in[12];
    const float* nvb    = (const float*)d_in[13];
    const float* rel_h  = (const float*)d_in[14];
    const float* rel_w  = (const float*)d_in[15];
    const float* rel_t  = (const float*)d_in[16];
    float* out = (float*)d_out;

    const int smem_bias = (125 * RSTRIDE + 128 * 96) * 4;
    cudaFuncSetAttribute(flash_mma_kernel, cudaFuncAttributeMaxDynamicSharedMemorySize, FLASH_SMEM);
    cudaFuncSetAttribute(bias_kernel, cudaFuncAttributeMaxDynamicSharedMemorySize, smem_bias);

    dim3 g1(99, 9);
    gemm_mma_kernel<<<g1, 256>>>(x, qkv_w, qkv_b, nullptr, NTOK, 576, 0);

    dim3 g2(785, 6);
    pool_kernel<<<g2, 256>>>(pqw, pkw, pvw, nqg, nqb, nkg, nkb, nvg, nvb);

    dim3 g3(49, 2);
    bias_kernel<<<g3, 256, smem_bias>>>(rel_h, rel_w, rel_t);

    dim3 gp(NT_TILES, 2);
    prep_kernel<<<gp, 256>>>();

    dim3 g4(66, 2);
    flash_mma_kernel<<<g4, 384, FLASH_SMEM>>>();

    dim3 g5(99, 3);
    gemm_mma_kernel<<<g5, 256>>>(nullptr, proj_w, proj_b, out, NTOK, 192, 1);
}

// round 16
// speedup vs baseline: 2.1903x; 1.0403x over previous
#include <cuda_runtime.h>
#include <cuda_bf16.h>
#include <cstdint>
#include <math.h>

#define T_    8
#define H_    28
#define W_    28
#define SP_   6272
#define NTOK  6273
#define DIM_  192
#define HD_   96
#define BROW  68
#define SCALE_ 0.1020620726159658f   // 96^-0.5
#define LOG2E  1.4426950408889634f
#define SCL2   (SCALE_ * LOG2E)
#define NT_TILES 99
#define NKT 10

// Scratch (static device memory — no allocations)
__device__ float g_raw [6 * NTOK * HD_];
__device__ float g_pool[6 * NTOK * HD_];
__device__ float g_bias[2 * NTOK * BROW];
__device__ float g_att [NTOK * DIM_];
__device__ unsigned g_kimg[2 * NT_TILES * 5120];  // K_ext fragment images (paired kt)
__device__ unsigned g_vimg[2 * NT_TILES * 3328];  // V fragment images (paired)

// ---------------------------------------------------------------------------
__device__ __forceinline__ float cvt_tf32(float x) {
    unsigned u; asm("cvt.rna.tf32.f32 %0, %1;" : "=r"(u) : "f"(x));
    return __uint_as_float(u);
}
__device__ __forceinline__ float fexp2(float x) {
    float y; asm("ex2.approx.ftz.f32 %0, %1;" : "=f"(y) : "f"(x)); return y;
}
__device__ __forceinline__ unsigned pack_bf16(float x, float y) {
    __nv_bfloat162 h = __float22bfloat162_rn(make_float2(x, y));
    return *(unsigned*)&h;
}
__device__ __forceinline__ void mma8(float* d, const float4& a, const float2& b) {
    asm volatile("mma.sync.aligned.m16n8k8.row.col.f32.tf32.tf32.f32 "
        "{%0,%1,%2,%3}, {%4,%5,%6,%7}, {%8,%9}, {%0,%1,%2,%3};"
        : "+f"(d[0]), "+f"(d[1]), "+f"(d[2]), "+f"(d[3])
        : "r"(__float_as_uint(a.x)), "r"(__float_as_uint(a.y)),
          "r"(__float_as_uint(a.z)), "r"(__float_as_uint(a.w)),
          "r"(__float_as_uint(b.x)), "r"(__float_as_uint(b.y)));
}
__device__ __forceinline__ void mma16(float* d, const float4& a, const float2& b) {
    asm volatile("mma.sync.aligned.m16n8k16.row.col.f32.bf16.bf16.f32 "
        "{%0,%1,%2,%3}, {%4,%5,%6,%7}, {%8,%9}, {%0,%1,%2,%3};"
        : "+f"(d[0]), "+f"(d[1]), "+f"(d[2]), "+f"(d[3])
        : "r"(__float_as_uint(a.x)), "r"(__float_as_uint(a.y)),
          "r"(__float_as_uint(a.z)), "r"(__float_as_uint(a.w)),
          "r"(__float_as_uint(b.x)), "r"(__float_as_uint(b.y)));
}
__device__ __forceinline__ unsigned smem_u32(const void* p) {
    unsigned a;
    asm("{ .reg .u64 t; cvta.to.shared.u64 t, %1; cvt.u32.u64 %0, t; }" : "=r"(a) : "l"(p));
    return a;
}
__device__ __forceinline__ void cp16(unsigned s, const void* g) {
    asm volatile("cp.async.cg.shared.global [%0], [%1], 16;" :: "r"(s), "l"(g) : "memory");
}
#define CP_COMMIT() asm volatile("cp.async.commit_group;" ::: "memory")
#define CP_WAIT0()  asm volatile("cp.async.wait_group 0;" ::: "memory")

// ---------------------------------------------------------------------------
// tf32 mma GEMM  (unchanged, known-good)
// ---------------------------------------------------------------------------
__global__ __launch_bounds__(256) void gemm_mma_kernel(
    const float* __restrict__ A, const float* __restrict__ Bm,
    const float* __restrict__ bias, float* __restrict__ out,
    int M, int N, int mode)
{
    __shared__ float sA[6144];
    __shared__ float sB[6144];
    const float* Ap = (mode == 1) ? g_att : A;

    int tid = threadIdx.x, lane = tid & 31, warp = tid >> 5;
    int mw = warp >> 1, nh = warp & 1;
    int m0 = blockIdx.x * 64, n0 = blockIdx.y * 64;

    float d[4][4] = {};

    for (int k0 = 0; k0 < 192; k0 += 96) {
        __syncthreads();
        {
            int r_g = tid >> 2, r = r_g & 15, mt = r_g >> 4;
            int row = m0 + r_g; if (row >= M) row = M - 1;
            #pragma unroll
            for (int c4 = tid & 3; c4 < 24; c4 += 4) {
                float4 v = *(const float4*)(Ap + row * 192 + k0 + c4 * 4);
                int base = (mt * 12 + (c4 >> 1)) * 128 + (r & 7) * 16
                           + ((r >> 3) & 1) + 2 * (c4 & 1);
                sA[base + 0]  = cvt_tf32(v.x); sA[base + 4]  = cvt_tf32(v.y);
                sA[base + 8]  = cvt_tf32(v.z); sA[base + 12] = cvt_tf32(v.w);
            }
        }
        {
            int r_g = tid >> 2;
            int nt = r_g >> 3, gn = r_g & 7;
            #pragma unroll
            for (int c4 = tid & 3; c4 < 24; c4 += 4) {
                float4 v = *(const float4*)(Bm + (n0 + r_g) * 192 + k0 + c4 * 4);
                int base = (nt * 12 + (c4 >> 1)) * 64 + gn * 8 + (c4 & 1);
                sB[base + 0] = cvt_tf32(v.x); sB[base + 2] = cvt_tf32(v.y);
                sB[base + 4] = cvt_tf32(v.z); sB[base + 6] = cvt_tf32(v.w);
            }
        }
        __syncthreads();
        #pragma unroll
        for (int kt = 0; kt < 12; kt++) {
            float4 a = *(const float4*)(sA + ((mw * 12 + kt) * 32 + lane) * 4);
            #pragma unroll
            for (int nt = 0; nt < 4; nt++) {
                float2 b = *(const float2*)(sB + (((nh * 4 + nt) * 12 + kt) * 32 + lane) * 2);
                mma8(d[nt], a, b);
            }
        }
    }

    int g = lane >> 2, tq = lane & 3;
    int r0 = m0 + mw * 16 + g, r1 = r0 + 8;
    #pragma unroll
    for (int nt = 0; nt < 4; nt++) {
        int col = n0 + nh * 32 + nt * 8 + tq * 2;
        #pragma unroll
        for (int e = 0; e < 2; e++) {
            int c = col + e;
            float b = bias[c];
            float v0 = d[nt][e]     + b;
            float v1 = d[nt][e + 2] + b;
            if (mode == 0) {
                int which = c / DIM_;
                int rem   = c - which * DIM_;
                int head  = rem / HD_;
                int cc    = rem - head * HD_;
                int base  = (which * 2 + head) * NTOK * HD_ + cc;
                if (r0 < M) g_raw[base + r0 * HD_] = v0;
                if (r1 < M) g_raw[base + r1 * HD_] = v1;
            } else {
                if (r0 < M) out[r0 * N + c] = v0;
                if (r1 < M) out[r1 * N + c] = v1;
            }
        }
    }
}

// ---------------------------------------------------------------------------
// Attention pool (unchanged): 1 warp/token, smem weights, shuffle LN
// ---------------------------------------------------------------------------
__global__ __launch_bounds__(256) void pool_kernel(
    const float* __restrict__ wq, const float* __restrict__ wk, const float* __restrict__ wv,
    const float* __restrict__ gq, const float* __restrict__ bq,
    const float* __restrict__ gk, const float* __restrict__ bk,
    const float* __restrict__ gv, const float* __restrict__ bv)
{
    __shared__ float sW[27 * 96];
    int tid = threadIdx.x;
    int yy  = blockIdx.y;
    int tensor = yy >> 1, head = yy & 1;

    const float* wc = (tensor == 0) ? wq : (tensor == 1) ? wk : wv;
    const float* g  = (tensor == 0) ? gq : (tensor == 1) ? gk : gv;
    const float* b  = (tensor == 0) ? bq : (tensor == 1) ? bk : bv;

    for (int i = tid; i < 27 * 96; i += 256) {
        int tap = i / 96, c = i - tap * 96;
        sW[i] = wc[c * 27 + tap];
    }
    __syncthreads();

    int w = tid >> 5, lane = tid & 31;
    int tok = blockIdx.x * 8 + w;
    if (tok < NTOK) {
        const float* in = g_raw + (tensor * 2 + head) * NTOK * HD_;
        float v0, v1, v2;
        if (tok == 0) {
            v0 = in[lane]; v1 = in[lane + 32]; v2 = in[lane + 64];
        } else {
            int s = tok - 1;
            int t = s / 784; int r = s - t * 784;
            int h = r / 28;  int ww = r - h * 28;
            v0 = v1 = v2 = 0.f;
            #pragma unroll
            for (int dt = -1; dt <= 1; dt++) {
                int tt = t + dt; if ((unsigned)tt >= (unsigned)T_) continue;
                #pragma unroll
                for (int dh = -1; dh <= 1; dh++) {
                    int hh = h + dh; if ((unsigned)hh >= (unsigned)H_) continue;
                    #pragma unroll
                    for (int dw = -1; dw <= 1; dw++) {
                        int w2 = ww + dw; if ((unsigned)w2 >= (unsigned)W_) continue;
                        int nb = 1 + (tt * 28 + hh) * 28 + w2;
                        int tap = (dt + 1) * 9 + (dh + 1) * 3 + (dw + 1);
                        const float* p  = in + nb * 96;
                        const float* wr = sW + tap * 96;
                        v0 += p[lane]      * wr[lane];
                        v1 += p[lane + 32] * wr[lane + 32];
                        v2 += p[lane + 64] * wr[lane + 64];
                    }
                }
            }
        }
        float s1 = v0 + v1 + v2;
        float s2 = v0 * v0 + v1 * v1 + v2 * v2;
        #pragma unroll
        for (int o = 1; o < 32; o <<= 1) {
            s1 += __shfl_xor_sync(0xffffffffu, s1, o);
            s2 += __shfl_xor_sync(0xffffffffu, s2, o);
        }
        float mean = s1 * (1.f / 96.f);
        float var  = s2 * (1.f / 96.f) - mean * mean;
        float is   = rsqrtf(var + 1e-5f);
        float* outp = g_pool + (tensor * 2 + head) * NTOK * HD_ + tok * 96;
        outp[lane]      = (v0 - mean) * is * g[lane]      + b[lane];
        outp[lane + 32] = (v1 - mean) * is * g[lane + 32] + b[lane + 32];
        outp[lane + 64] = (v2 - mean) * is * g[lane + 64] + b[lane + 64];
    }
}

// ---------------------------------------------------------------------------
// Rel-bias precompute (unchanged; output ×LOG2E)
#define RSTRIDE 100
__global__ __launch_bounds__(256) void bias_kernel(
    const float* __restrict__ rel_h, const float* __restrict__ rel_w,
    const float* __restrict__ rel_t)
{
    extern __shared__ float bsm[];
    float* sRel = bsm;
    float* sQ   = bsm + 125 * RSTRIDE;
    int head = blockIdx.y;
    int qb = blockIdx.x * 128;
    int tid = threadIdx.x;
    const float* qp = g_pool + head * NTOK * HD_;

    if (blockIdx.x == 0 && tid < BROW)
        g_bias[(head * NTOK) * BROW + tid] = 0.f;

    for (int idx = tid; idx < 125 * 24; idx += 256) {
        int row = idx / 24, c4 = idx - row * 24;
        const float* src = row < 15 ? rel_t + row * 96
                         : row < 70 ? rel_h + (row - 15) * 96
                                    : rel_w + (row - 70) * 96;
        float4 v = *(const float4*)(src + c4 * 4);
        float* dst = sRel + row * RSTRIDE + c4 * 4;
        dst[0] = v.x * LOG2E; dst[1] = v.y * LOG2E;
        dst[2] = v.z * LOG2E; dst[3] = v.w * LOG2E;
    }
    for (int idx = tid; idx < 128 * 24; idx += 256) {
        int r = idx / 24, c4 = idx - r * 24;
        *(float4*)(sQ + r * 96 + c4 * 4) =
            *(const float4*)(qp + (qb + 1 + r) * 96 + c4 * 4);
    }
    __syncthreads();

    for (int it = tid; it < 128 * 64; it += 256) {
        int ql = it >> 6, i = it & 63;
        int s = qb + ql;
        int t = s / 784; int rr = s - t * 784;
        int h = rr / 28; int w = rr - h * 28;
        int row = (i < 8)  ? (t - i + 7)
                : (i < 36) ? 15 + (h - (i - 8) + 27)
                           : 70 + (w - (i - 36) + 27);
        const float* q4 = sQ + ql * 96;
        const float* r4 = sRel + row * RSTRIDE;
        float sum = 0.f;
        #pragma unroll
        for (int c = 0; c < 96; c += 4) {
            float4 a = *(const float4*)(q4 + c);
            float4 b = *(const float4*)(r4 + c);
            sum += a.x*b.x + a.y*b.y + a.z*b.z + a.w*b.w;
        }
        g_bias[(head * NTOK + s + 1) * BROW + i] = sum;
    }
    for (int idx = tid; idx < 128 * 4; idx += 256) {
        int ql = idx >> 2, i = 64 + (idx & 3);
        g_bias[(head * NTOK + qb + 1 + ql) * BROW + i] = 0.f;
    }
}

// ---------------------------------------------------------------------------
// Prep: build K_ext (160ch, kt-PAIRED fragment layout) and V images.
// K word = (nt*5 + (kt>>1))*128 + (gnk*4 + (p&3))*4 + (kt&1)*2 + (p>>2)
// grid (99, 2), 256 threads.
// ---------------------------------------------------------------------------
__global__ __launch_bounds__(256) void prep_kernel()
{
    int tile = blockIdx.x, head = blockIdx.y;
    int tid = threadIdx.x;
    unsigned* kimg = g_kimg + (head * NT_TILES + tile) * 5120;
    unsigned* vimg = g_vimg + (head * NT_TILES + tile) * 3328;
    const float* kp = g_pool + (2 + head) * NTOK * HD_;
    const float* vp = g_pool + (4 + head) * NTOK * HD_;

    // K_ext: 64 keys x 40 c4-chunks
    for (int idx = tid; idx < 2560; idx += 256) {
        int r = idx / 40, c4 = idx - r * 40;
        int rowg = tile * 64 + r;
        float4 kv = make_float4(0.f, 0.f, 0.f, 0.f);
        if (rowg < NTOK) {
            if (c4 < 24) {
                const float* s = kp + rowg * 96 + c4 * 4;
                kv = make_float4(s[0] * SCL2, s[1] * SCL2, s[2] * SCL2, s[3] * SCL2);
            } else if (rowg > 0) {
                int ss = rowg - 1;
                int t = ss / 784; int rr = ss - t * 784;
                int hh = rr / 28; int ww = rr - hh * 28;
                int i0 = t, i1 = 8 + hh, i2 = 36 + ww;
                int base = (c4 - 24) * 4;
                float* a = &kv.x;
                #pragma unroll
                for (int e = 0; e < 4; e++) {
                    int pos = base + e;
                    if (pos == i0 || pos == i1 || pos == i2) a[e] = 1.f;
                }
            }
        }
        int ntk = r >> 3, gnk = r & 7;
        int p0 = 2 * c4;
        int kt = p0 >> 3, p = p0 & 7;
        unsigned* dK = kimg + (ntk * 5 + (kt >> 1)) * 128;
        int half = (kt & 1) * 2;
        dK[(gnk * 4 + (p & 3)) * 4 + half + (p >> 2)]   = pack_bf16(kv.x, kv.y);
        int p1 = p + 1;
        dK[(gnk * 4 + (p1 & 3)) * 4 + half + (p1 >> 2)] = pack_bf16(kv.z, kv.w);
    }
    // V: 32 key-pairs x 25 c4-chunks -> paired B-fragment layout
    for (int idx = tid; idx < 800; idx += 256) {
        int jp = idx / 25, c4 = idx - jp * 25;
        int j0 = tile * 64 + 2 * jp, j1 = j0 + 1;
        int ktv = jp >> 3, pv = jp & 7;
        int koff = (ktv >> 1) * 128 + (pv & 3) * 4 + (ktv & 1) * 2 + (pv >> 2);
        if (c4 < 24) {
            float4 v0 = (j0 < NTOK) ? *(const float4*)(vp + j0 * 96 + c4 * 4)
                                    : make_float4(0.f, 0.f, 0.f, 0.f);
            float4 v1 = (j1 < NTOK) ? *(const float4*)(vp + j1 * 96 + c4 * 4)
                                    : make_float4(0.f, 0.f, 0.f, 0.f);
            float a0[4] = {v0.x, v0.y, v0.z, v0.w};
            float a1[4] = {v1.x, v1.y, v1.z, v1.w};
            #pragma unroll
            for (int j = 0; j < 4; j++) {
                int c = c4 * 4 + j;
                int ntv = c >> 3, gnv = c & 7;
                vimg[ntv * 256 + gnv * 16 + koff] = pack_bf16(a0[j], a1[j]);
            }
        } else {
            vimg[12 * 256 + 0 + koff] = pack_bf16(j0 < NTOK ? 1.f : 0.f,
                                                  j1 < NTOK ? 1.f : 0.f);
            #pragma unroll
            for (int gnv = 1; gnv < 8; gnv++)
                vimg[12 * 256 + gnv * 16 + koff] = 0u;
        }
    }
}

// ---------------------------------------------------------------------------
// Flash attention v10: bias folded into 160-dim S-mma; paired K LDS.128;
// cp.async staging; register Q_ext; fixed-shift softmax + ones-column l.
// grid (66,2), block 384.
// ---------------------------------------------------------------------------
#define SQ_OFF  0        // 6 mt * 10 kt * 128 = 7680 words
#define SK_OFF  7680     // 2 buf * 5120
#define SV_OFF  17920    // 2 buf * 3328
#define FLASH_SMEM (24576 * 4)
#define OSTR 100

__device__ __forceinline__ void cp_stage(unsigned sbyte, int head, int t, int buf, int tid)
{
    const uint4* ks = (const uint4*)(g_kimg + (head * NT_TILES + t) * 5120);
    unsigned kd = sbyte + (SK_OFF + buf * 5120) * 4;
    for (int i = tid; i < 1280; i += 384) cp16(kd + i * 16, ks + i);
    const uint4* vs = (const uint4*)(g_vimg + (head * NT_TILES + t) * 3328);
    unsigned vd = sbyte + (SV_OFF + buf * 3328) * 4;
    for (int i = tid; i < 832; i += 384) cp16(vd + i * 16, vs + i);
}

__global__ __launch_bounds__(384, 1) void flash_mma_kernel()
{
    extern __shared__ float sm[];
    float* sQp = sm + SQ_OFF;
    unsigned sbyte = smem_u32(sm);

    const int head = blockIdx.y;
    const int q0 = blockIdx.x * 96;
    const int tid = threadIdx.x;
    const int lane = tid & 31, warp = tid >> 5;
    const int mw = warp >> 1, nw = warp & 1;

    const float* qp = g_pool + head * NTOK * HD_;

    // kick off tile 0 copies
    cp_stage(sbyte, head, 0, 0, tid);
    CP_COMMIT();

    // Q_ext = [q (96), bias row ×LOG2E (64)] -> bf16 A-fragment layout
    {
        int r_g = tid >> 2;
        int row = q0 + r_g;
        bool ok = row < NTOK;
        int mt = r_g >> 4, r = r_g & 15;
        int rh = (r >> 3) & 1;
        const float* brow = g_bias + (head * NTOK + (ok ? row : 0)) * BROW;
        #pragma unroll
        for (int c4 = tid & 3; c4 < 40; c4 += 4) {
            float4 v = make_float4(0.f, 0.f, 0.f, 0.f);
            if (ok) {
                v = (c4 < 24) ? *(const float4*)(qp + row * 96 + c4 * 4)
                              : *(const float4*)(brow + (c4 - 24) * 4);
            }
            int p0 = 2 * c4;
            int kt = p0 >> 3, p = p0 & 7;
            unsigned* dst = (unsigned*)sQp + (mt * NKT + kt) * 128;
            dst[((r & 7) * 4 + (p & 3)) * 4 + rh + 2 * (p >> 2)]   = pack_bf16(v.x, v.y);
            int p1 = p + 1;
            dst[((r & 7) * 4 + (p1 & 3)) * 4 + rh + 2 * (p1 >> 2)] = pack_bf16(v.z, v.w);
        }
    }
    CP_WAIT0();
    __syncthreads();

    // hoist Q_ext fragments (tile-invariant)
    float4 aq[NKT];
    #pragma unroll
    for (int kt = 0; kt < NKT; kt++)
        aq[kt] = *(const float4*)(sQp + ((mw * NKT + kt) * 32 + lane) * 4);

    float oacc[13][4] = {};

    for (int t = 0; t < NT_TILES; t++) {
        int buf = t & 1;
        if (t + 1 < NT_TILES) {
            cp_stage(sbyte, head, t + 1, buf ^ 1, tid);
            CP_COMMIT();
        }

        float* sKb = sm + SK_OFF + buf * 5120;
        float* sVb = sm + SV_OFF + buf * 3328;

        // S_log2 = Q_ext K_ext^T (scale+bias inside; paired K LDS.128)
        float d[4][4] = {};
        #pragma unroll
        for (int ktp = 0; ktp < 5; ktp++) {
            #pragma unroll
            for (int nt = 0; nt < 4; nt++) {
                float4 b4 = *(const float4*)(sKb + (((nw * 4 + nt) * 5 + ktp) * 32 + lane) * 4);
                mma16(d[nt], aq[2 * ktp],     make_float2(b4.x, b4.y));
                mma16(d[nt], aq[2 * ktp + 1], make_float2(b4.z, b4.w));
            }
        }

        // p = exp2(d)  (fixed-shift softmax; no mask needed)
        unsigned pk[2][4];
        #pragma unroll
        for (int nt = 0; nt < 4; nt++) {
            pk[nt >> 1][(nt & 1) * 2 + 0] = pack_bf16(fexp2(d[nt][0]), fexp2(d[nt][1]));
            pk[nt >> 1][(nt & 1) * 2 + 1] = pack_bf16(fexp2(d[nt][2]), fexp2(d[nt][3]));
        }

        // O += P V  (paired LDS.128; 13th nt = l via ones column)
        float4 af0 = make_float4(__uint_as_float(pk[0][0]), __uint_as_float(pk[0][1]),
                                 __uint_as_float(pk[0][2]), __uint_as_float(pk[0][3]));
        float4 af1 = make_float4(__uint_as_float(pk[1][0]), __uint_as_float(pk[1][1]),
                                 __uint_as_float(pk[1][2]), __uint_as_float(pk[1][3]));
        #pragma unroll
        for (int nt = 0; nt < 13; nt++) {
            float4 b4 = *(const float4*)(sVb + (nt * 2 + nw) * 128 + lane * 4);
            mma16(oacc[nt], af0, make_float2(b4.x, b4.y));
            mma16(oacc[nt], af1, make_float2(b4.z, b4.w));
        }

        if (t + 1 < NT_TILES) {
            CP_WAIT0();
            __syncthreads();
        }
    }

    // extract l (ones channel, col 96), combine split-KV halves
    float lA = __shfl_sync(0xffffffffu, oacc[12][0], lane & 28);
    float lB = __shfl_sync(0xffffffffu, oacc[12][2], lane & 28);

    __syncthreads();
    float* sO  = sm;                 // 96 * OSTR
    float* sLl = sm + 96 * OSTR;     // 96
    int g = lane >> 2, tq = lane & 3;
    int rl0 = mw * 16 + g, rl1 = rl0 + 8;

    if (nw == 1) {
        #pragma unroll
        for (int nt = 0; nt < 12; nt++) {
            *(float2*)(sO + rl0 * OSTR + nt * 8 + tq * 2) = make_float2(oacc[nt][0], oacc[nt][1]);
            *(float2*)(sO + rl1 * OSTR + nt * 8 + tq * 2) = make_float2(oacc[nt][2], oacc[nt][3]);
        }
        if (tq == 0) { sLl[rl0] = lA; sLl[rl1] = lB; }
    }
    __syncthreads();
    if (nw == 0) {
        float inv0 = 1.f / (lA + sLl[rl0]);
        float inv1 = 1.f / (lB + sLl[rl1]);
        int r0 = q0 + rl0, r1 = q0 + rl1;
        #pragma unroll
        for (int nt = 0; nt < 12; nt++) {
            int c = nt * 8 + tq * 2;
            if (r0 < NTOK) {
                float2 o1 = *(float2*)(sO + rl0 * OSTR + c);
                float x0 = (oacc[nt][0] + o1.x) * inv0;
                float x1 = (oacc[nt][1] + o1.y) * inv0;
                if (r0 >= 1) { x0 += qp[r0 * 96 + c]; x1 += qp[r0 * 96 + c + 1]; }
                g_att[r0 * 192 + head * 96 + c]     = x0;
                g_att[r0 * 192 + head * 96 + c + 1] = x1;
            }
            if (r1 < NTOK) {
                float2 o1 = *(float2*)(sO + rl1 * OSTR + c);
                float x0 = (oacc[nt][2] + o1.x) * inv1;
                float x1 = (oacc[nt][3] + o1.y) * inv1;
                x0 += qp[r1 * 96 + c]; x1 += qp[r1 * 96 + c + 1];
                g_att[r1 * 192 + head * 96 + c]     = x0;
                g_att[r1 * 192 + head * 96 + c + 1] = x1;
            }
        }
    }
}

// ---------------------------------------------------------------------------
extern "C" void kernel_launch(void* const* d_in, const int* in_sizes, int n_in,
                              void* d_out, int out_size)
{
    const float* x      = (const float*)d_in[0];
    const float* qkv_w  = (const float*)d_in[1];
    const float* qkv_b  = (const float*)d_in[2];
    const float* proj_w = (const float*)d_in[3];
    const float* proj_b = (const float*)d_in[4];
    const float* pqw    = (const float*)d_in[5];
    const float* pkw    = (const float*)d_in[6];
    const float* pvw    = (const float*)d_in[7];
    const float* nqg    = (const float*)d_in[8];
    const float* nqb    = (const float*)d_in[9];
    const float* nkg    = (const float*)d_in[10];
    const float* nkb    = (const float*)d_in[11];
    const float* nvg    = (const float*)d_in[12];
    const float* nvb    = (const float*)d_in[13];
    const float* rel_h  = (const float*)d_in[14];
    const float* rel_w  = (const float*)d_in[15];
    const float* rel_t  = (const float*)d_in[16];
    float* out = (float*)d_out;

    const int smem_bias = (125 * RSTRIDE + 128 * 96) * 4;
    cudaFuncSetAttribute(flash_mma_kernel, cudaFuncAttributeMaxDynamicSharedMemorySize, FLASH_SMEM);
    cudaFuncSetAttribute(bias_kernel, cudaFuncAttributeMaxDynamicSharedMemorySize, smem_bias);

    dim3 g1(99, 9);
    gemm_mma_kernel<<<g1, 256>>>(x, qkv_w, qkv_b, nullptr, NTOK, 576, 0);

    dim3 g2(785, 6);
    pool_kernel<<<g2, 256>>>(pqw, pkw, pvw, nqg, nqb, nkg, nkb, nvg, nvb);

    dim3 g3(49, 2);
    bias_kernel<<<g3, 256, smem_bias>>>(rel_h, rel_w, rel_t);

    dim3 gp(NT_TILES, 2);
    prep_kernel<<<gp, 256>>>();

    dim3 g4(66, 2);
    flash_mma_kernel<<<g4, 384, FLASH_SMEM>>>();

    dim3 g5(99, 3);
    gemm_mma_kernel<<<g5, 256>>>(nullptr, proj_w, proj_b, out, NTOK, 192, 1);
}

// round 17
// speedup vs baseline: 2.3030x; 1.0514x over previous
#include <cuda_runtime.h>
#include <cuda_bf16.h>
#include <cstdint>
#include <math.h>

#define T_    8
#define H_    28
#define W_    28
#define SP_   6272
#define NTOK  6273
#define DIM_  192
#define HD_   96
#define BROW  68
#define SCALE_ 0.1020620726159658f   // 96^-0.5
#define LOG2E  1.4426950408889634f
#define SCL2   (SCALE_ * LOG2E)
#define NT_TILES 99
#define NKT 10

// Scratch (static device memory — no allocations)
__device__ float g_raw [6 * NTOK * HD_];
__device__ float g_pool[6 * NTOK * HD_];
__device__ float g_bias[2 * NTOK * BROW];
__device__ float g_att [NTOK * DIM_];
__device__ unsigned g_kimg[2 * NT_TILES * 5120];  // K_ext fragment images (paired kt)
__device__ unsigned g_vimg[2 * NT_TILES * 3328];  // V fragment images (paired)
__device__ float g_ximg [99 * 2 * 6144];          // x A-fragment image (tf32)
__device__ float g_wimg [9 * 2 * 6144];           // qkv_w B-fragment image
__device__ float g_pwimg[3 * 2 * 6144];           // proj_w B-fragment image

// ---------------------------------------------------------------------------
__device__ __forceinline__ float cvt_tf32(float x) {
    unsigned u; asm("cvt.rna.tf32.f32 %0, %1;" : "=r"(u) : "f"(x));
    return __uint_as_float(u);
}
__device__ __forceinline__ float fexp2(float x) {
    float y; asm("ex2.approx.ftz.f32 %0, %1;" : "=f"(y) : "f"(x)); return y;
}
__device__ __forceinline__ unsigned pack_bf16(float x, float y) {
    __nv_bfloat162 h = __float22bfloat162_rn(make_float2(x, y));
    return *(unsigned*)&h;
}
__device__ __forceinline__ void mma8(float* d, const float4& a, const float2& b) {
    asm volatile("mma.sync.aligned.m16n8k8.row.col.f32.tf32.tf32.f32 "
        "{%0,%1,%2,%3}, {%4,%5,%6,%7}, {%8,%9}, {%0,%1,%2,%3};"
        : "+f"(d[0]), "+f"(d[1]), "+f"(d[2]), "+f"(d[3])
        : "r"(__float_as_uint(a.x)), "r"(__float_as_uint(a.y)),
          "r"(__float_as_uint(a.z)), "r"(__float_as_uint(a.w)),
          "r"(__float_as_uint(b.x)), "r"(__float_as_uint(b.y)));
}
__device__ __forceinline__ void mma16(float* d, const float4& a, const float2& b) {
    asm volatile("mma.sync.aligned.m16n8k16.row.col.f32.bf16.bf16.f32 "
        "{%0,%1,%2,%3}, {%4,%5,%6,%7}, {%8,%9}, {%0,%1,%2,%3};"
        : "+f"(d[0]), "+f"(d[1]), "+f"(d[2]), "+f"(d[3])
        : "r"(__float_as_uint(a.x)), "r"(__float_as_uint(a.y)),
          "r"(__float_as_uint(a.z)), "r"(__float_as_uint(a.w)),
          "r"(__float_as_uint(b.x)), "r"(__float_as_uint(b.y)));
}
__device__ __forceinline__ unsigned smem_u32(const void* p) {
    unsigned a;
    asm("{ .reg .u64 t; cvta.to.shared.u64 t, %1; cvt.u32.u64 %0, t; }" : "=r"(a) : "l"(p));
    return a;
}
__device__ __forceinline__ void cp16(unsigned s, const void* g) {
    asm volatile("cp.async.cg.shared.global [%0], [%1], 16;" :: "r"(s), "l"(g) : "memory");
}
#define CP_COMMIT() asm volatile("cp.async.commit_group;" ::: "memory")
#define CP_WAIT0()  asm volatile("cp.async.wait_group 0;" ::: "memory")
#define CP_WAIT1()  asm volatile("cp.async.wait_group 1;" ::: "memory")

// ---------------------------------------------------------------------------
// Prep GEMM images: x -> A-frag (tf32), qkv_w / proj_w -> B-frag.
// grid 222 blocks x 256.
// ---------------------------------------------------------------------------
__global__ __launch_bounds__(256) void prep_gemm_kernel(
    const float* __restrict__ x, const float* __restrict__ qkv_w,
    const float* __restrict__ proj_w)
{
    int bx = blockIdx.x, tid = threadIdx.x;
    if (bx < 198) {
        int mb = bx >> 1, kc = bx & 1;
        float* dst = g_ximg + (mb * 2 + kc) * 6144;
        for (int idx = tid; idx < 1536; idx += 256) {
            int r_g = idx / 24, c4 = idx - r_g * 24;
            int row = mb * 64 + r_g; if (row >= NTOK) row = NTOK - 1;
            float4 v = *(const float4*)(x + row * 192 + kc * 96 + c4 * 4);
            int r = r_g & 15, mt = r_g >> 4;
            int base = (mt * 12 + (c4 >> 1)) * 128 + (r & 7) * 16
                       + ((r >> 3) & 1) + 2 * (c4 & 1);
            dst[base + 0]  = cvt_tf32(v.x); dst[base + 4]  = cvt_tf32(v.y);
            dst[base + 8]  = cvt_tf32(v.z); dst[base + 12] = cvt_tf32(v.w);
        }
    } else {
        int i = bx - 198;
        const float* W; float* dst;
        if (i < 18) { W = qkv_w;  dst = g_wimg  + i * 6144; }
        else        { i -= 18; W = proj_w; dst = g_pwimg + i * 6144; }
        int nb = i >> 1, kc = i & 1;
        for (int idx = tid; idx < 1536; idx += 256) {
            int r_g = idx / 24, c4 = idx - r_g * 24;
            float4 v = *(const float4*)(W + (nb * 64 + r_g) * 192 + kc * 96 + c4 * 4);
            int nt = r_g >> 3, gn = r_g & 7;
            int base = (nt * 12 + (c4 >> 1)) * 64 + gn * 8 + (c4 & 1);
            dst[base + 0] = cvt_tf32(v.x); dst[base + 2] = cvt_tf32(v.y);
            dst[base + 4] = cvt_tf32(v.z); dst[base + 6] = cvt_tf32(v.w);
        }
    }
}

// ---------------------------------------------------------------------------
// QKV GEMM: pure cp.async from images. grid (99, 9), 256 thr, dyn smem 96KB.
// ---------------------------------------------------------------------------
__global__ __launch_bounds__(256) void qkv_gemm_kernel(const float* __restrict__ bias)
{
    extern __shared__ float gsm[];
    unsigned sbyte = smem_u32(gsm);
    int tid = threadIdx.x, lane = tid & 31, warp = tid >> 5;
    int mw = warp >> 1, nh = warp & 1;
    int mb = blockIdx.x, nb = blockIdx.y;

    // copy both chunks: A then B per chunk, one commit group per chunk
    #pragma unroll
    for (int kc = 0; kc < 2; kc++) {
        const uint4* as = (const uint4*)(g_ximg + (mb * 2 + kc) * 6144);
        const uint4* bs = (const uint4*)(g_wimg + (nb * 2 + kc) * 6144);
        unsigned ad = sbyte + kc * 49152;
        unsigned bd = sbyte + kc * 49152 + 24576;
        for (int i = tid; i < 1536; i += 256) cp16(ad + i * 16, as + i);
        for (int i = tid; i < 1536; i += 256) cp16(bd + i * 16, bs + i);
        CP_COMMIT();
    }

    float d[4][4] = {};
    CP_WAIT1();
    __syncthreads();
    #pragma unroll
    for (int kc = 0; kc < 2; kc++) {
        float* sA = gsm + kc * 12288;
        float* sB = gsm + kc * 12288 + 6144;
        if (kc == 1) { CP_WAIT0(); __syncthreads(); }
        #pragma unroll
        for (int kt = 0; kt < 12; kt++) {
            float4 a = *(const float4*)(sA + ((mw * 12 + kt) * 32 + lane) * 4);
            #pragma unroll
            for (int nt = 0; nt < 4; nt++) {
                float2 b = *(const float2*)(sB + (((nh * 4 + nt) * 12 + kt) * 32 + lane) * 2);
                mma8(d[nt], a, b);
            }
        }
    }

    int g = lane >> 2, tq = lane & 3;
    int r0 = mb * 64 + mw * 16 + g, r1 = r0 + 8;
    #pragma unroll
    for (int nt = 0; nt < 4; nt++) {
        int col = nb * 64 + nh * 32 + nt * 8 + tq * 2;
        #pragma unroll
        for (int e = 0; e < 2; e++) {
            int c = col + e;
            float b = bias[c];
            float v0 = d[nt][e]     + b;
            float v1 = d[nt][e + 2] + b;
            int which = c / DIM_;
            int rem   = c - which * DIM_;
            int head  = rem / HD_;
            int cc    = rem - head * HD_;
            int base  = (which * 2 + head) * NTOK * HD_ + cc;
            if (r0 < NTOK) g_raw[base + r0 * HD_] = v0;
            if (r1 < NTOK) g_raw[base + r1 * HD_] = v1;
        }
    }
}

// ---------------------------------------------------------------------------
// Proj GEMM: A staged from g_att (scalar), B via cp.async image.
// grid (99, 3), 256 thr, dyn smem 72KB.
// ---------------------------------------------------------------------------
__global__ __launch_bounds__(256) void proj_gemm_kernel(
    const float* __restrict__ bias, float* __restrict__ out)
{
    extern __shared__ float gsm[];   // sA 6144 | sB0 6144 | sB1 6144
    unsigned sbyte = smem_u32(gsm);
    float* sA = gsm;
    int tid = threadIdx.x, lane = tid & 31, warp = tid >> 5;
    int mw = warp >> 1, nh = warp & 1;
    int m0 = blockIdx.x * 64, nb = blockIdx.y;

    #pragma unroll
    for (int kc = 0; kc < 2; kc++) {
        const uint4* bs = (const uint4*)(g_pwimg + (nb * 2 + kc) * 6144);
        unsigned bd = sbyte + 24576 + kc * 24576;
        for (int i = tid; i < 1536; i += 256) cp16(bd + i * 16, bs + i);
    }
    CP_COMMIT();

    float d[4][4] = {};
    #pragma unroll
    for (int kc = 0; kc < 2; kc++) {
        __syncthreads();
        {
            int r_g = tid >> 2, r = r_g & 15, mt = r_g >> 4;
            int row = m0 + r_g; if (row >= NTOK) row = NTOK - 1;
            #pragma unroll
            for (int c4 = tid & 3; c4 < 24; c4 += 4) {
                float4 v = *(const float4*)(g_att + row * 192 + kc * 96 + c4 * 4);
                int base = (mt * 12 + (c4 >> 1)) * 128 + (r & 7) * 16
                           + ((r >> 3) & 1) + 2 * (c4 & 1);
                sA[base + 0]  = cvt_tf32(v.x); sA[base + 4]  = cvt_tf32(v.y);
                sA[base + 8]  = cvt_tf32(v.z); sA[base + 12] = cvt_tf32(v.w);
            }
        }
        if (kc == 0) CP_WAIT0();
        __syncthreads();
        float* sB = gsm + 6144 + kc * 6144;
        #pragma unroll
        for (int kt = 0; kt < 12; kt++) {
            float4 a = *(const float4*)(sA + ((mw * 12 + kt) * 32 + lane) * 4);
            #pragma unroll
            for (int nt = 0; nt < 4; nt++) {
                float2 b = *(const float2*)(sB + (((nh * 4 + nt) * 12 + kt) * 32 + lane) * 2);
                mma8(d[nt], a, b);
            }
        }
    }

    int g = lane >> 2, tq = lane & 3;
    int r0 = m0 + mw * 16 + g, r1 = r0 + 8;
    #pragma unroll
    for (int nt = 0; nt < 4; nt++) {
        int col = nb * 64 + nh * 32 + nt * 8 + tq * 2;
        #pragma unroll
        for (int e = 0; e < 2; e++) {
            int c = col + e;
            float b = bias[c];
            if (r0 < NTOK) out[r0 * 192 + c] = d[nt][e]     + b;
            if (r1 < NTOK) out[r1 * 192 + c] = d[nt][e + 2] + b;
        }
    }
}

// ---------------------------------------------------------------------------
// Attention pool (unchanged): 1 warp/token, smem weights, shuffle LN
// ---------------------------------------------------------------------------
__global__ __launch_bounds__(256) void pool_kernel(
    const float* __restrict__ wq, const float* __restrict__ wk, const float* __restrict__ wv,
    const float* __restrict__ gq, const float* __restrict__ bq,
    const float* __restrict__ gk, const float* __restrict__ bk,
    const float* __restrict__ gv, const float* __restrict__ bv)
{
    __shared__ float sW[27 * 96];
    int tid = threadIdx.x;
    int yy  = blockIdx.y;
    int tensor = yy >> 1, head = yy & 1;

    const float* wc = (tensor == 0) ? wq : (tensor == 1) ? wk : wv;
    const float* g  = (tensor == 0) ? gq : (tensor == 1) ? gk : gv;
    const float* b  = (tensor == 0) ? bq : (tensor == 1) ? bk : bv;

    for (int i = tid; i < 27 * 96; i += 256) {
        int tap = i / 96, c = i - tap * 96;
        sW[i] = wc[c * 27 + tap];
    }
    __syncthreads();

    int w = tid >> 5, lane = tid & 31;
    int tok = blockIdx.x * 8 + w;
    if (tok < NTOK) {
        const float* in = g_raw + (tensor * 2 + head) * NTOK * HD_;
        float v0, v1, v2;
        if (tok == 0) {
            v0 = in[lane]; v1 = in[lane + 32]; v2 = in[lane + 64];
        } else {
            int s = tok - 1;
            int t = s / 784; int r = s - t * 784;
            int h = r / 28;  int ww = r - h * 28;
            v0 = v1 = v2 = 0.f;
            #pragma unroll
            for (int dt = -1; dt <= 1; dt++) {
                int tt = t + dt; if ((unsigned)tt >= (unsigned)T_) continue;
                #pragma unroll
                for (int dh = -1; dh <= 1; dh++) {
                    int hh = h + dh; if ((unsigned)hh >= (unsigned)H_) continue;
                    #pragma unroll
                    for (int dw = -1; dw <= 1; dw++) {
                        int w2 = ww + dw; if ((unsigned)w2 >= (unsigned)W_) continue;
                        int nb = 1 + (tt * 28 + hh) * 28 + w2;
                        int tap = (dt + 1) * 9 + (dh + 1) * 3 + (dw + 1);
                        const float* p  = in + nb * 96;
                        const float* wr = sW + tap * 96;
                        v0 += p[lane]      * wr[lane];
                        v1 += p[lane + 32] * wr[lane + 32];
                        v2 += p[lane + 64] * wr[lane + 64];
                    }
                }
            }
        }
        float s1 = v0 + v1 + v2;
        float s2 = v0 * v0 + v1 * v1 + v2 * v2;
        #pragma unroll
        for (int o = 1; o < 32; o <<= 1) {
            s1 += __shfl_xor_sync(0xffffffffu, s1, o);
            s2 += __shfl_xor_sync(0xffffffffu, s2, o);
        }
        float mean = s1 * (1.f / 96.f);
        float var  = s2 * (1.f / 96.f) - mean * mean;
        float is   = rsqrtf(var + 1e-5f);
        float* outp = g_pool + (tensor * 2 + head) * NTOK * HD_ + tok * 96;
        outp[lane]      = (v0 - mean) * is * g[lane]      + b[lane];
        outp[lane + 32] = (v1 - mean) * is * g[lane + 32] + b[lane + 32];
        outp[lane + 64] = (v2 - mean) * is * g[lane + 64] + b[lane + 64];
    }
}

// ---------------------------------------------------------------------------
// Rel-bias precompute (unchanged; output ×LOG2E)
#define RSTRIDE 100
__global__ __launch_bounds__(256) void bias_kernel(
    const float* __restrict__ rel_h, const float* __restrict__ rel_w,
    const float* __restrict__ rel_t)
{
    extern __shared__ float bsm[];
    float* sRel = bsm;
    float* sQ   = bsm + 125 * RSTRIDE;
    int head = blockIdx.y;
    int qb = blockIdx.x * 128;
    int tid = threadIdx.x;
    const float* qp = g_pool + head * NTOK * HD_;

    if (blockIdx.x == 0 && tid < BROW)
        g_bias[(head * NTOK) * BROW + tid] = 0.f;

    for (int idx = tid; idx < 125 * 24; idx += 256) {
        int row = idx / 24, c4 = idx - row * 24;
        const float* src = row < 15 ? rel_t + row * 96
                         : row < 70 ? rel_h + (row - 15) * 96
                                    : rel_w + (row - 70) * 96;
        float4 v = *(const float4*)(src + c4 * 4);
        float* dst = sRel + row * RSTRIDE + c4 * 4;
        dst[0] = v.x * LOG2E; dst[1] = v.y * LOG2E;
        dst[2] = v.z * LOG2E; dst[3] = v.w * LOG2E;
    }
    for (int idx = tid; idx < 128 * 24; idx += 256) {
        int r = idx / 24, c4 = idx - r * 24;
        *(float4*)(sQ + r * 96 + c4 * 4) =
            *(const float4*)(qp + (qb + 1 + r) * 96 + c4 * 4);
    }
    __syncthreads();

    for (int it = tid; it < 128 * 64; it += 256) {
        int ql = it >> 6, i = it & 63;
        int s = qb + ql;
        int t = s / 784; int rr = s - t * 784;
        int h = rr / 28; int w = rr - h * 28;
        int row = (i < 8)  ? (t - i + 7)
                : (i < 36) ? 15 + (h - (i - 8) + 27)
                           : 70 + (w - (i - 36) + 27);
        const float* q4 = sQ + ql * 96;
        const float* r4 = sRel + row * RSTRIDE;
        float sum = 0.f;
        #pragma unroll
        for (int c = 0; c < 96; c += 4) {
            float4 a = *(const float4*)(q4 + c);
            float4 b = *(const float4*)(r4 + c);
            sum += a.x*b.x + a.y*b.y + a.z*b.z + a.w*b.w;
        }
        g_bias[(head * NTOK + s + 1) * BROW + i] = sum;
    }
    for (int idx = tid; idx < 128 * 4; idx += 256) {
        int ql = idx >> 2, i = 64 + (idx & 3);
        g_bias[(head * NTOK + qb + 1 + ql) * BROW + i] = 0.f;
    }
}

// ---------------------------------------------------------------------------
// Prep KV: K_ext (160ch, kt-paired) and V images (unchanged R15)
// ---------------------------------------------------------------------------
__global__ __launch_bounds__(256) void prep_kernel()
{
    int tile = blockIdx.x, head = blockIdx.y;
    int tid = threadIdx.x;
    unsigned* kimg = g_kimg + (head * NT_TILES + tile) * 5120;
    unsigned* vimg = g_vimg + (head * NT_TILES + tile) * 3328;
    const float* kp = g_pool + (2 + head) * NTOK * HD_;
    const float* vp = g_pool + (4 + head) * NTOK * HD_;

    for (int idx = tid; idx < 2560; idx += 256) {
        int r = idx / 40, c4 = idx - r * 40;
        int rowg = tile * 64 + r;
        float4 kv = make_float4(0.f, 0.f, 0.f, 0.f);
        if (rowg < NTOK) {
            if (c4 < 24) {
                const float* s = kp + rowg * 96 + c4 * 4;
                kv = make_float4(s[0] * SCL2, s[1] * SCL2, s[2] * SCL2, s[3] * SCL2);
            } else if (rowg > 0) {
                int ss = rowg - 1;
                int t = ss / 784; int rr = ss - t * 784;
                int hh = rr / 28; int ww = rr - hh * 28;
                int i0 = t, i1 = 8 + hh, i2 = 36 + ww;
                int base = (c4 - 24) * 4;
                float* a = &kv.x;
                #pragma unroll
                for (int e = 0; e < 4; e++) {
                    int pos = base + e;
                    if (pos == i0 || pos == i1 || pos == i2) a[e] = 1.f;
                }
            }
        }
        int ntk = r >> 3, gnk = r & 7;
        int p0 = 2 * c4;
        int kt = p0 >> 3, p = p0 & 7;
        unsigned* dK = kimg + (ntk * 5 + (kt >> 1)) * 128;
        int half = (kt & 1) * 2;
        dK[(gnk * 4 + (p & 3)) * 4 + half + (p >> 2)]   = pack_bf16(kv.x, kv.y);
        int p1 = p + 1;
        dK[(gnk * 4 + (p1 & 3)) * 4 + half + (p1 >> 2)] = pack_bf16(kv.z, kv.w);
    }
    for (int idx = tid; idx < 800; idx += 256) {
        int jp = idx / 25, c4 = idx - jp * 25;
        int j0 = tile * 64 + 2 * jp, j1 = j0 + 1;
        int ktv = jp >> 3, pv = jp & 7;
        int koff = (ktv >> 1) * 128 + (pv & 3) * 4 + (ktv & 1) * 2 + (pv >> 2);
        if (c4 < 24) {
            float4 v0 = (j0 < NTOK) ? *(const float4*)(vp + j0 * 96 + c4 * 4)
                                    : make_float4(0.f, 0.f, 0.f, 0.f);
            float4 v1 = (j1 < NTOK) ? *(const float4*)(vp + j1 * 96 + c4 * 4)
                                    : make_float4(0.f, 0.f, 0.f, 0.f);
            float a0[4] = {v0.x, v0.y, v0.z, v0.w};
            float a1[4] = {v1.x, v1.y, v1.z, v1.w};
            #pragma unroll
            for (int j = 0; j < 4; j++) {
                int c = c4 * 4 + j;
                int ntv = c >> 3, gnv = c & 7;
                vimg[ntv * 256 + gnv * 16 + koff] = pack_bf16(a0[j], a1[j]);
            }
        } else {
            vimg[12 * 256 + 0 + koff] = pack_bf16(j0 < NTOK ? 1.f : 0.f,
                                                  j1 < NTOK ? 1.f : 0.f);
            #pragma unroll
            for (int gnv = 1; gnv < 8; gnv++)
                vimg[12 * 256 + gnv * 16 + koff] = 0u;
        }
    }
}

// ---------------------------------------------------------------------------
// Flash attention v10 (unchanged R15 winner)
// ---------------------------------------------------------------------------
#define SQ_OFF  0
#define SK_OFF  7680
#define SV_OFF  17920
#define FLASH_SMEM (24576 * 4)
#define OSTR 100

__device__ __forceinline__ void cp_stage(unsigned sbyte, int head, int t, int buf, int tid)
{
    const uint4* ks = (const uint4*)(g_kimg + (head * NT_TILES + t) * 5120);
    unsigned kd = sbyte + (SK_OFF + buf * 5120) * 4;
    for (int i = tid; i < 1280; i += 384) cp16(kd + i * 16, ks + i);
    const uint4* vs = (const uint4*)(g_vimg + (head * NT_TILES + t) * 3328);
    unsigned vd = sbyte + (SV_OFF + buf * 3328) * 4;
    for (int i = tid; i < 832; i += 384) cp16(vd + i * 16, vs + i);
}

__global__ __launch_bounds__(384, 1) void flash_mma_kernel()
{
    extern __shared__ float sm[];
    float* sQp = sm + SQ_OFF;
    unsigned sbyte = smem_u32(sm);

    const int head = blockIdx.y;
    const int q0 = blockIdx.x * 96;
    const int tid = threadIdx.x;
    const int lane = tid & 31, warp = tid >> 5;
    const int mw = warp >> 1, nw = warp & 1;

    const float* qp = g_pool + head * NTOK * HD_;

    cp_stage(sbyte, head, 0, 0, tid);
    CP_COMMIT();

    {
        int r_g = tid >> 2;
        int row = q0 + r_g;
        bool ok = row < NTOK;
        int mt = r_g >> 4, r = r_g & 15;
        int rh = (r >> 3) & 1;
        const float* brow = g_bias + (head * NTOK + (ok ? row : 0)) * BROW;
        #pragma unroll
        for (int c4 = tid & 3; c4 < 40; c4 += 4) {
            float4 v = make_float4(0.f, 0.f, 0.f, 0.f);
            if (ok) {
                v = (c4 < 24) ? *(const float4*)(qp + row * 96 + c4 * 4)
                              : *(const float4*)(brow + (c4 - 24) * 4);
            }
            int p0 = 2 * c4;
            int kt = p0 >> 3, p = p0 & 7;
            unsigned* dst = (unsigned*)sQp + (mt * NKT + kt) * 128;
            dst[((r & 7) * 4 + (p & 3)) * 4 + rh + 2 * (p >> 2)]   = pack_bf16(v.x, v.y);
            int p1 = p + 1;
            dst[((r & 7) * 4 + (p1 & 3)) * 4 + rh + 2 * (p1 >> 2)] = pack_bf16(v.z, v.w);
        }
    }
    CP_WAIT0();
    __syncthreads();

    float4 aq[NKT];
    #pragma unroll
    for (int kt = 0; kt < NKT; kt++)
        aq[kt] = *(const float4*)(sQp + ((mw * NKT + kt) * 32 + lane) * 4);

    float oacc[13][4] = {};

    for (int t = 0; t < NT_TILES; t++) {
        int buf = t & 1;
        if (t + 1 < NT_TILES) {
            cp_stage(sbyte, head, t + 1, buf ^ 1, tid);
            CP_COMMIT();
        }

        float* sKb = sm + SK_OFF + buf * 5120;
        float* sVb = sm + SV_OFF + buf * 3328;

        float d[4][4] = {};
        #pragma unroll
        for (int ktp = 0; ktp < 5; ktp++) {
            #pragma unroll
            for (int nt = 0; nt < 4; nt++) {
                float4 b4 = *(const float4*)(sKb + (((nw * 4 + nt) * 5 + ktp) * 32 + lane) * 4);
                mma16(d[nt], aq[2 * ktp],     make_float2(b4.x, b4.y));
                mma16(d[nt], aq[2 * ktp + 1], make_float2(b4.z, b4.w));
            }
        }

        unsigned pk[2][4];
        #pragma unroll
        for (int nt = 0; nt < 4; nt++) {
            pk[nt >> 1][(nt & 1) * 2 + 0] = pack_bf16(fexp2(d[nt][0]), fexp2(d[nt][1]));
            pk[nt >> 1][(nt & 1) * 2 + 1] = pack_bf16(fexp2(d[nt][2]), fexp2(d[nt][3]));
        }

        float4 af0 = make_float4(__uint_as_float(pk[0][0]), __uint_as_float(pk[0][1]),
                                 __uint_as_float(pk[0][2]), __uint_as_float(pk[0][3]));
        float4 af1 = make_float4(__uint_as_float(pk[1][0]), __uint_as_float(pk[1][1]),
                                 __uint_as_float(pk[1][2]), __uint_as_float(pk[1][3]));
        #pragma unroll
        for (int nt = 0; nt < 13; nt++) {
            float4 b4 = *(const float4*)(sVb + (nt * 2 + nw) * 128 + lane * 4);
            mma16(oacc[nt], af0, make_float2(b4.x, b4.y));
            mma16(oacc[nt], af1, make_float2(b4.z, b4.w));
        }

        if (t + 1 < NT_TILES) {
            CP_WAIT0();
            __syncthreads();
        }
    }

    float lA = __shfl_sync(0xffffffffu, oacc[12][0], lane & 28);
    float lB = __shfl_sync(0xffffffffu, oacc[12][2], lane & 28);

    __syncthreads();
    float* sO  = sm;
    float* sLl = sm + 96 * OSTR;
    int g = lane >> 2, tq = lane & 3;
    int rl0 = mw * 16 + g, rl1 = rl0 + 8;

    if (nw == 1) {
        #pragma unroll
        for (int nt = 0; nt < 12; nt++) {
            *(float2*)(sO + rl0 * OSTR + nt * 8 + tq * 2) = make_float2(oacc[nt][0], oacc[nt][1]);
            *(float2*)(sO + rl1 * OSTR + nt * 8 + tq * 2) = make_float2(oacc[nt][2], oacc[nt][3]);
        }
        if (tq == 0) { sLl[rl0] = lA; sLl[rl1] = lB; }
    }
    __syncthreads();
    if (nw == 0) {
        float inv0 = 1.f / (lA + sLl[rl0]);
        float inv1 = 1.f / (lB + sLl[rl1]);
        int r0 = q0 + rl0, r1 = q0 + rl1;
        #pragma unroll
        for (int nt = 0; nt < 12; nt++) {
            int c = nt * 8 + tq * 2;
            if (r0 < NTOK) {
                float2 o1 = *(float2*)(sO + rl0 * OSTR + c);
                float x0 = (oacc[nt][0] + o1.x) * inv0;
                float x1 = (oacc[nt][1] + o1.y) * inv0;
                if (r0 >= 1) { x0 += qp[r0 * 96 + c]; x1 += qp[r0 * 96 + c + 1]; }
                g_att[r0 * 192 + head * 96 + c]     = x0;
                g_att[r0 * 192 + head * 96 + c + 1] = x1;
            }
            if (r1 < NTOK) {
                float2 o1 = *(float2*)(sO + rl1 * OSTR + c);
                float x0 = (oacc[nt][2] + o1.x) * inv1;
                float x1 = (oacc[nt][3] + o1.y) * inv1;
                x0 += qp[r1 * 96 + c]; x1 += qp[r1 * 96 + c + 1];
                g_att[r1 * 192 + head * 96 + c]     = x0;
                g_att[r1 * 192 + head * 96 + c + 1] = x1;
            }
        }
    }
}

// ---------------------------------------------------------------------------
extern "C" void kernel_launch(void* const* d_in, const int* in_sizes, int n_in,
                              void* d_out, int out_size)
{
    const float* x      = (const float*)d_in[0];
    const float* qkv_w  = (const float*)d_in[1];
    const float* qkv_b  = (const float*)d_in[2];
    const float* proj_w = (const float*)d_in[3];
    const float* proj_b = (const float*)d_in[4];
    const float* pqw    = (const float*)d_in[5];
    const float* pkw    = (const float*)d_in[6];
    const float* pvw    = (const float*)d_in[7];
    const float* nqg    = (const float*)d_in[8];
    const float* nqb    = (const float*)d_in[9];
    const float* nkg    = (const float*)d_in[10];
    const float* nkb    = (const float*)d_in[11];
    const float* nvg    = (const float*)d_in[12];
    const float* nvb    = (const float*)d_in[13];
    const float* rel_h  = (const float*)d_in[14];
    const float* rel_w  = (const float*)d_in[15];
    const float* rel_t  = (const float*)d_in[16];
    float* out = (float*)d_out;

    const int smem_bias = (125 * RSTRIDE + 128 * 96) * 4;
    const int smem_qkv  = 24576 * 4;   // 98304
    const int smem_proj = 18432 * 4;   // 73728
    cudaFuncSetAttribute(flash_mma_kernel, cudaFuncAttributeMaxDynamicSharedMemorySize, FLASH_SMEM);
    cudaFuncSetAttribute(bias_kernel, cudaFuncAttributeMaxDynamicSharedMemorySize, smem_bias);
    cudaFuncSetAttribute(qkv_gemm_kernel, cudaFuncAttributeMaxDynamicSharedMemorySize, smem_qkv);
    cudaFuncSetAttribute(proj_gemm_kernel, cudaFuncAttributeMaxDynamicSharedMemorySize, smem_proj);

    prep_gemm_kernel<<<222, 256>>>(x, qkv_w, proj_w);

    dim3 g1(99, 9);
    qkv_gemm_kernel<<<g1, 256, smem_qkv>>>(qkv_b);

    dim3 g2(785, 6);
    pool_kernel<<<g2, 256>>>(pqw, pkw, pvw, nqg, nqb, nkg, nkb, nvg, nvb);

    dim3 g3(49, 2);
    bias_kernel<<<g3, 256, smem_bias>>>(rel_h, rel_w, rel_t);

    dim3 gp(NT_TILES, 2);
    prep_kernel<<<gp, 256>>>();

    dim3 g4(66, 2);
    flash_mma_kernel<<<g4, 384, FLASH_SMEM>>>();

    dim3 g5(99, 3);
    proj_gemm_kernel<<<g5, 256, smem_proj>>>(proj_b, out);
}